// round 3
// baseline (speedup 1.0000x reference)
#include <cuda_runtime.h>
#include <cuda_bf16.h>
#include <math.h>

// Problem constants
#define BATCH 4
#define SEQ   2048
#define DMODEL 1024
#define NHEAD 16
#define HDIM  64
#define DFF   4096
#define TOKENS (BATCH*SEQ)       // 8192
#define MODW  6144               // 6*D

// ---------------- scratch (device globals; no allocations allowed) ----------
__device__ float g_mod[BATCH * MODW];                 // adaLN modulation (4,6144)
__device__ float g_xn[(size_t)TOKENS * DMODEL];       // normed+modulated activations
__device__ float g_qkv[(size_t)TOKENS * 3 * DMODEL];  // qkv (B,S,3,H,HD)
__device__ float g_attn[(size_t)TOKENS * DMODEL];     // attention output (B,S,D)
__device__ float g_h[(size_t)TOKENS * DFF];           // MLP hidden

// ---------------- helpers ---------------------------------------------------
__device__ __forceinline__ float warpSum(float v) {
    v += __shfl_xor_sync(0xffffffffu, v, 16);
    v += __shfl_xor_sync(0xffffffffu, v, 8);
    v += __shfl_xor_sync(0xffffffffu, v, 4);
    v += __shfl_xor_sync(0xffffffffu, v, 2);
    v += __shfl_xor_sync(0xffffffffu, v, 1);
    return v;
}

__device__ __forceinline__ float gelu_tanh(float x) {
    float x3 = x * x * x;
    return 0.5f * x * (1.0f + tanhf(0.7978845608028654f * (x + 0.044715f * x3)));
}

// ---------------- K0: adaLN modulation: mod = c @ ada_W + ada_b --------------
// c: (4,1024), ada_W: (1024,6144) row-major, mod: (4,6144)
__global__ void ada_kernel(const float* __restrict__ c,
                           const float* __restrict__ W,
                           const float* __restrict__ bias,
                           float* __restrict__ mod) {
    __shared__ float cs[BATCH * 1024];
    int tid = threadIdx.x;
    for (int i = tid; i < BATCH * 1024; i += 256) cs[i] = c[i];
    __syncthreads();
    int n = blockIdx.x * 256 + tid;
    float a0 = 0.f, a1 = 0.f, a2 = 0.f, a3 = 0.f;
    #pragma unroll 4
    for (int k = 0; k < 1024; k++) {
        float w = W[(size_t)k * MODW + n];
        a0 += cs[k] * w;
        a1 += cs[1024 + k] * w;
        a2 += cs[2048 + k] * w;
        a3 += cs[3072 + k] * w;
    }
    float bb = bias[n];
    mod[n] = a0 + bb;
    mod[MODW + n] = a1 + bb;
    mod[2 * MODW + n] = a2 + bb;
    mod[3 * MODW + n] = a3 + bb;
}

// ---------------- K1: LayerNorm + modulate ----------------------------------
// out = LN(x)*w * (1 + mod[b, scOff+d]) + mod[b, shOff+d]
__global__ void ln_mod_kernel(const float* __restrict__ x,
                              const float* __restrict__ w,
                              const float* __restrict__ mod,
                              int shOff, int scOff,
                              float* __restrict__ out) {
    int token = blockIdx.x;
    int b = token >> 11;   // token / 2048
    int tid = threadIdx.x;
    const float* xr = x + (size_t)token * DMODEL;
    float v[4];
    float lsum = 0.f, lsq = 0.f;
    #pragma unroll
    for (int i = 0; i < 4; i++) {
        v[i] = xr[i * 256 + tid];
        lsum += v[i];
        lsq  += v[i] * v[i];
    }
    __shared__ float s1[8], s2[8];
    float ws = warpSum(lsum), wq = warpSum(lsq);
    int warp = tid >> 5, lane = tid & 31;
    if (lane == 0) { s1[warp] = ws; s2[warp] = wq; }
    __syncthreads();
    __shared__ float s_mu, s_rstd;
    if (tid == 0) {
        float ts = 0.f, tq = 0.f;
        #pragma unroll
        for (int i = 0; i < 8; i++) { ts += s1[i]; tq += s2[i]; }
        float mu = ts * (1.0f / DMODEL);
        float var = tq * (1.0f / DMODEL) - mu * mu;
        s_mu = mu;
        s_rstd = rsqrtf(var + 1e-5f);
    }
    __syncthreads();
    float mu = s_mu, rstd = s_rstd;
    const float* mrow = mod + (size_t)b * MODW;
    float* orow = out + (size_t)token * DMODEL;
    #pragma unroll
    for (int i = 0; i < 4; i++) {
        int d = i * 256 + tid;
        float xn = (v[i] - mu) * rstd * w[d];
        orow[d] = xn * (1.f + mrow[scOff + d]) + mrow[shOff + d];
    }
}

// ---------------- K2: 128x128x8 SGEMM with fused epilogues -------------------
// EPI 0: C = A@B
// EPI 1: C = gelu(A@B + bias)
// EPI 2: C = resid + mod[b, modOff+n] * (A@B)              (N must be 1024)
// EPI 3: C = resid + mod[b, modOff+n] * (A@B + bias)       (N must be 1024)
template <int EPI>
__global__ void gemm128(const float* __restrict__ A, const float* __restrict__ B,
                        float* __restrict__ C, int M, int N, int K,
                        const float* __restrict__ bias,
                        const float* __restrict__ resid,
                        const float* __restrict__ mod, int modOff) {
    __shared__ float As[8][132];
    __shared__ float Bs[8][128];
    int bx = blockIdx.x, by = blockIdx.y;
    int tid = threadIdx.x;
    int tx = tid & 15, ty = tid >> 4;
    const float* Ablk = A + (size_t)by * 128 * K;
    const float* Bblk = B + (size_t)bx * 128;
    int arow = tid >> 1, acol4 = (tid & 1) * 4;
    int brow = tid >> 5, bcol4 = (tid & 31) * 4;
    float acc[8][8];
    #pragma unroll
    for (int i = 0; i < 8; i++)
        #pragma unroll
        for (int j = 0; j < 8; j++) acc[i][j] = 0.f;

    for (int kt = 0; kt < K; kt += 8) {
        float4 av = *(const float4*)(Ablk + (size_t)arow * K + kt + acol4);
        float4 bv = *(const float4*)(Bblk + (size_t)(kt + brow) * N + bcol4);
        __syncthreads();
        As[acol4 + 0][arow] = av.x;
        As[acol4 + 1][arow] = av.y;
        As[acol4 + 2][arow] = av.z;
        As[acol4 + 3][arow] = av.w;
        *(float4*)&Bs[brow][bcol4] = bv;
        __syncthreads();
        #pragma unroll
        for (int k = 0; k < 8; k++) {
            float a[8], b[8];
            #pragma unroll
            for (int i = 0; i < 8; i++) a[i] = As[k][ty * 8 + i];
            #pragma unroll
            for (int j = 0; j < 8; j++) b[j] = Bs[k][tx * 8 + j];
            #pragma unroll
            for (int i = 0; i < 8; i++)
                #pragma unroll
                for (int j = 0; j < 8; j++)
                    acc[i][j] = fmaf(a[i], b[j], acc[i][j]);
        }
    }

    int row0 = by * 128 + ty * 8;
    int col0 = bx * 128 + tx * 8;
    #pragma unroll
    for (int i = 0; i < 8; i++) {
        int m = row0 + i;
        const float* mrow = (EPI >= 2) ? (mod + (size_t)(m >> 11) * MODW + modOff) : nullptr;
        #pragma unroll
        for (int j = 0; j < 8; j++) {
            int n = col0 + j;
            float v = acc[i][j];
            if (EPI == 1) v = gelu_tanh(v + bias[n]);
            if (EPI == 2) v = resid[(size_t)m * N + n] + mrow[n] * v;
            if (EPI == 3) v = resid[(size_t)m * N + n] + mrow[n] * (v + bias[n]);
            C[(size_t)m * N + n] = v;
        }
    }
}

// ---------------- K3: RMSNorm + RoPE on q,k (in-place in g_qkv) --------------
// one warp per (token, head, {q|k})
__global__ void rope_kernel(float* __restrict__ qkv,
                            const float* __restrict__ cosb,
                            const float* __restrict__ sinb,
                            const float* __restrict__ qw,
                            const float* __restrict__ kw) {
    int gwid = blockIdx.x * 8 + (threadIdx.x >> 5);
    int lane = threadIdx.x & 31;
    int bs = gwid >> 5;            // / (H*2)
    int rem = gwid & 31;
    int h = rem >> 1;
    int t = rem & 1;               // 0 = q, 1 = k
    float* base = qkv + (((size_t)bs * 3 + t) * NHEAD + h) * HDIM;
    const float* w = (t == 0) ? qw : kw;
    int s = bs & (SEQ - 1);
    float x0 = base[lane];
    float x1 = base[lane + 32];
    float ss = warpSum(x0 * x0 + x1 * x1);
    float rinv = rsqrtf(ss * (1.0f / HDIM) + 1e-6f);
    float n0 = x0 * rinv * w[lane];
    float n1 = x1 * rinv * w[lane + 32];
    const float* cr = cosb + (size_t)s * HDIM;
    const float* sr = sinb + (size_t)s * HDIM;
    float c0 = cr[lane], c1 = cr[lane + 32];
    float s0 = sr[lane], s1 = sr[lane + 32];
    base[lane]      = n0 * c0 - n1 * s0;
    base[lane + 32] = n1 * c1 + n0 * s1;
}

// ---------------- K4: flash-style attention ----------------------------------
// grid (B*H, S/64), 256 threads, dynamic smem
__global__ void flash_attn(const float* __restrict__ qkv, float* __restrict__ out) {
    extern __shared__ float sm[];
    float* Qs = sm;                   // 64*65
    float* Ks = Qs + 64 * 65;         // 64*65
    float* Ss = Ks + 64 * 65;         // 64*65
    float* Vs = Ss + 64 * 65;         // 64*64 (16B aligned: 12480 floats offset)
    float* mS = Vs + 64 * 64;
    float* lS = mS + 64;
    float* aS = lS + 64;

    int b = blockIdx.x >> 4, h = blockIdx.x & 15;
    int q0 = blockIdx.y * 64;
    int tid = threadIdx.x;

    // Q tile (scaled by 1/sqrt(HD))
    for (int idx = tid; idx < 1024; idx += 256) {
        int r = idx >> 4, c = (idx & 15) * 4;
        const float* p = qkv + (((size_t)(b * SEQ + q0 + r) * 3 + 0) * NHEAD + h) * HDIM + c;
        float4 v = *(const float4*)p;
        Qs[r * 65 + c + 0] = v.x * 0.125f;
        Qs[r * 65 + c + 1] = v.y * 0.125f;
        Qs[r * 65 + c + 2] = v.z * 0.125f;
        Qs[r * 65 + c + 3] = v.w * 0.125f;
    }
    if (tid < 64) { mS[tid] = -1e30f; lS[tid] = 0.f; }

    float o[16];
    #pragma unroll
    for (int j = 0; j < 16; j++) o[j] = 0.f;
    int orow = tid & 63;
    int obase = (tid >> 6) * 16;
    int sr0 = (tid & 15) * 4;
    int sk0 = (tid >> 4) * 4;

    for (int kt = 0; kt < SEQ / 64; kt++) {
        __syncthreads();
        int k0 = kt * 64;
        for (int idx = tid; idx < 1024; idx += 256) {
            int r = idx >> 4, c = (idx & 15) * 4;
            const float* pk = qkv + (((size_t)(b * SEQ + k0 + r) * 3 + 1) * NHEAD + h) * HDIM + c;
            const float* pv = qkv + (((size_t)(b * SEQ + k0 + r) * 3 + 2) * NHEAD + h) * HDIM + c;
            float4 kv = *(const float4*)pk;
            Ks[r * 65 + c + 0] = kv.x;
            Ks[r * 65 + c + 1] = kv.y;
            Ks[r * 65 + c + 2] = kv.z;
            Ks[r * 65 + c + 3] = kv.w;
            *(float4*)&Vs[r * 64 + c] = *(const float4*)pv;
        }
        __syncthreads();

        // scores: 4x4 microtile per thread
        float sacc[4][4];
        #pragma unroll
        for (int i = 0; i < 4; i++)
            #pragma unroll
            for (int j = 0; j < 4; j++) sacc[i][j] = 0.f;
        #pragma unroll 4
        for (int d = 0; d < 64; d++) {
            float qa[4], kb[4];
            #pragma unroll
            for (int i = 0; i < 4; i++) qa[i] = Qs[(sr0 + i) * 65 + d];
            #pragma unroll
            for (int j = 0; j < 4; j++) kb[j] = Ks[(sk0 + j) * 65 + d];
            #pragma unroll
            for (int i = 0; i < 4; i++)
                #pragma unroll
                for (int j = 0; j < 4; j++)
                    sacc[i][j] = fmaf(qa[i], kb[j], sacc[i][j]);
        }
        #pragma unroll
        for (int i = 0; i < 4; i++)
            #pragma unroll
            for (int j = 0; j < 4; j++)
                Ss[(sr0 + i) * 65 + sk0 + j] = sacc[i][j];
        __syncthreads();

        // online softmax (one thread per row)
        if (tid < 64) {
            int r = tid;
            float mold = mS[r], mnew = mold;
            #pragma unroll 8
            for (int kk = 0; kk < 64; kk++) mnew = fmaxf(mnew, Ss[r * 65 + kk]);
            float alpha = __expf(mold - mnew);
            float ls = 0.f;
            #pragma unroll 8
            for (int kk = 0; kk < 64; kk++) {
                float e = __expf(Ss[r * 65 + kk] - mnew);
                Ss[r * 65 + kk] = e;
                ls += e;
            }
            mS[r] = mnew;
            lS[r] = lS[r] * alpha + ls;
            aS[r] = alpha;
        }
        __syncthreads();

        // rescale + accumulate P@V
        float al = aS[orow];
        #pragma unroll
        for (int j = 0; j < 16; j++) o[j] *= al;
        #pragma unroll 4
        for (int kk = 0; kk < 64; kk++) {
            float p = Ss[orow * 65 + kk];
            const float4* vp = (const float4*)&Vs[kk * 64 + obase];
            float4 v0 = vp[0], v1 = vp[1], v2 = vp[2], v3 = vp[3];
            o[0]  = fmaf(p, v0.x, o[0]);   o[1]  = fmaf(p, v0.y, o[1]);
            o[2]  = fmaf(p, v0.z, o[2]);   o[3]  = fmaf(p, v0.w, o[3]);
            o[4]  = fmaf(p, v1.x, o[4]);   o[5]  = fmaf(p, v1.y, o[5]);
            o[6]  = fmaf(p, v1.z, o[6]);   o[7]  = fmaf(p, v1.w, o[7]);
            o[8]  = fmaf(p, v2.x, o[8]);   o[9]  = fmaf(p, v2.y, o[9]);
            o[10] = fmaf(p, v2.z, o[10]);  o[11] = fmaf(p, v2.w, o[11]);
            o[12] = fmaf(p, v3.x, o[12]);  o[13] = fmaf(p, v3.y, o[13]);
            o[14] = fmaf(p, v3.z, o[14]);  o[15] = fmaf(p, v3.w, o[15]);
        }
    }

    float inv = 1.f / lS[orow];
    float* op = out + (size_t)(b * SEQ + q0 + orow) * DMODEL + h * HDIM + obase;
    #pragma unroll
    for (int j = 0; j < 16; j++) op[j] = o[j] * inv;
}

// ---------------- launcher ---------------------------------------------------
extern "C" void kernel_launch(void* const* d_in, const int* in_sizes, int n_in,
                              void* d_out, int out_size) {
    const float* x       = (const float*)d_in[0];
    const float* cosb    = (const float*)d_in[1];
    const float* sinb    = (const float*)d_in[2];
    const float* c       = (const float*)d_in[3];
    const float* norm1_w = (const float*)d_in[4];
    const float* Wqkv    = (const float*)d_in[5];
    const float* Wout    = (const float*)d_in[6];
    const float* q_norm_w= (const float*)d_in[7];
    const float* k_norm_w= (const float*)d_in[8];
    const float* norm2_w = (const float*)d_in[9];
    const float* W1      = (const float*)d_in[10];
    const float* b1      = (const float*)d_in[11];
    const float* W2      = (const float*)d_in[12];
    const float* b2      = (const float*)d_in[13];
    const float* ada_W   = (const float*)d_in[14];
    const float* ada_b   = (const float*)d_in[15];
    float* out = (float*)d_out;

    float *mod_p, *xn_p, *qkv_p, *attn_p, *h_p;
    cudaGetSymbolAddress((void**)&mod_p, g_mod);
    cudaGetSymbolAddress((void**)&xn_p, g_xn);
    cudaGetSymbolAddress((void**)&qkv_p, g_qkv);
    cudaGetSymbolAddress((void**)&attn_p, g_attn);
    cudaGetSymbolAddress((void**)&h_p, g_h);

    // K0: modulation
    ada_kernel<<<MODW / 256, 256>>>(c, ada_W, ada_b, mod_p);

    // K1: LN1 + modulate (sh_msa @0, sc_msa @1024)
    ln_mod_kernel<<<TOKENS, 256>>>(x, norm1_w, mod_p, 0, 1024, xn_p);

    // K2: QKV GEMM (8192 x 3072 x 1024)
    gemm128<0><<<dim3(3 * DMODEL / 128, TOKENS / 128), 256>>>(
        xn_p, Wqkv, qkv_p, TOKENS, 3 * DMODEL, DMODEL, nullptr, nullptr, nullptr, 0);

    // K3: RMSNorm + RoPE on q,k
    rope_kernel<<<TOKENS * NHEAD * 2 / 8, 256>>>(qkv_p, cosb, sinb, q_norm_w, k_norm_w);

    // K4: attention
    int smem = (3 * 64 * 65 + 64 * 64 + 3 * 64) * sizeof(float);  // 67072 B
    cudaFuncSetAttribute(flash_attn, cudaFuncAttributeMaxDynamicSharedMemorySize, smem);
    flash_attn<<<dim3(BATCH * NHEAD, SEQ / 64), 256, smem>>>(qkv_p, attn_p);

    // K5: Wout GEMM + gated residual (g_msa @2048) -> d_out holds residual stream
    gemm128<2><<<dim3(DMODEL / 128, TOKENS / 128), 256>>>(
        attn_p, Wout, out, TOKENS, DMODEL, DMODEL, nullptr, x, mod_p, 2048);

    // K6: LN2 + modulate (sh_mlp @3072, sc_mlp @4096)
    ln_mod_kernel<<<TOKENS, 256>>>(out, norm2_w, mod_p, 3072, 4096, xn_p);

    // K7: MLP up GEMM + bias + gelu
    gemm128<1><<<dim3(DFF / 128, TOKENS / 128), 256>>>(
        xn_p, W1, h_p, TOKENS, DFF, DMODEL, b1, nullptr, nullptr, 0);

    // K8: MLP down GEMM + bias + gated residual (g_mlp @5120), in-place on d_out
    gemm128<3><<<dim3(DMODEL / 128, TOKENS / 128), 256>>>(
        h_p, W2, out, TOKENS, DMODEL, DFF, b2, out, mod_p, 5120);
}

// round 9
// speedup vs baseline: 1.0576x; 1.0576x over previous
#include <cuda_runtime.h>
#include <cuda_bf16.h>
#include <math.h>
#include <stdint.h>

// Problem constants
#define BATCH 4
#define SEQ   2048
#define DMODEL 1024
#define NHEAD 16
#define HDIM  64
#define DFF   4096
#define TOKENS (BATCH*SEQ)       // 8192
#define MODW  6144               // 6*D

// ---------------- scratch (device globals; no allocations allowed) ----------
__device__ float g_mod[BATCH * MODW];
__device__ float g_xn[(size_t)TOKENS * DMODEL];
__device__ float g_qkv[(size_t)TOKENS * 3 * DMODEL];
__device__ float g_attn[(size_t)TOKENS * DMODEL];
__device__ float g_h[(size_t)TOKENS * DFF];

// ---------------- generic helpers -------------------------------------------
__device__ __forceinline__ float warpSum(float v) {
    v += __shfl_xor_sync(0xffffffffu, v, 16);
    v += __shfl_xor_sync(0xffffffffu, v, 8);
    v += __shfl_xor_sync(0xffffffffu, v, 4);
    v += __shfl_xor_sync(0xffffffffu, v, 2);
    v += __shfl_xor_sync(0xffffffffu, v, 1);
    return v;
}

__device__ __forceinline__ float gelu_tanh(float x) {
    float x3 = x * x * x;
    return 0.5f * x * (1.0f + tanhf(0.7978845608028654f * (x + 0.044715f * x3)));
}

__device__ __forceinline__ uint32_t smem_u32(const void* p) {
    uint32_t a;
    asm("{ .reg .u64 t; cvta.to.shared.u64 t, %1; cvt.u32.u64 %0, t; }" : "=r"(a) : "l"(p));
    return a;
}

// fp32 -> (hi, lo) bf16 pair, packed two-at-a-time into b32
__device__ __forceinline__ uint32_t split_pack(float a, float b, uint32_t& lo) {
    __nv_bfloat16 ha = __float2bfloat16(a), hb = __float2bfloat16(b);
    float ra = a - __bfloat162float(ha);
    float rb = b - __bfloat162float(hb);
    __nv_bfloat16 la = __float2bfloat16(ra), lb = __float2bfloat16(rb);
    lo = (uint32_t)__bfloat16_as_ushort(la) | ((uint32_t)__bfloat16_as_ushort(lb) << 16);
    return (uint32_t)__bfloat16_as_ushort(ha) | ((uint32_t)__bfloat16_as_ushort(hb) << 16);
}

// ---------------- warp-level MMA primitives (sm_80+, no 'a' features) --------
__device__ __forceinline__ void ldsm4(uint32_t* r, uint32_t a) {
    asm volatile("ldmatrix.sync.aligned.m8n8.x4.shared.b16 {%0,%1,%2,%3}, [%4];"
        : "=r"(r[0]), "=r"(r[1]), "=r"(r[2]), "=r"(r[3]) : "r"(a));
}
__device__ __forceinline__ void ldsm4t(uint32_t* r, uint32_t a) {
    asm volatile("ldmatrix.sync.aligned.m8n8.x4.trans.shared.b16 {%0,%1,%2,%3}, [%4];"
        : "=r"(r[0]), "=r"(r[1]), "=r"(r[2]), "=r"(r[3]) : "r"(a));
}
__device__ __forceinline__ void mma16816(float* c, const uint32_t* a, const uint32_t* b) {
    asm volatile(
        "mma.sync.aligned.m16n8k16.row.col.f32.bf16.bf16.f32 "
        "{%0,%1,%2,%3}, {%4,%5,%6,%7}, {%8,%9}, {%0,%1,%2,%3};"
        : "+f"(c[0]), "+f"(c[1]), "+f"(c[2]), "+f"(c[3])
        : "r"(a[0]), "r"(a[1]), "r"(a[2]), "r"(a[3]), "r"(b[0]), "r"(b[1]));
}

// ---------------- K0: adaLN modulation ---------------------------------------
__global__ void ada_kernel(const float* __restrict__ c,
                           const float* __restrict__ W,
                           const float* __restrict__ bias,
                           float* __restrict__ mod) {
    __shared__ float cs[BATCH * 1024];
    int tid = threadIdx.x;
    for (int i = tid; i < BATCH * 1024; i += 256) cs[i] = c[i];
    __syncthreads();
    int n = blockIdx.x * 256 + tid;
    float a0 = 0.f, a1 = 0.f, a2 = 0.f, a3 = 0.f;
    #pragma unroll 4
    for (int k = 0; k < 1024; k++) {
        float w = W[(size_t)k * MODW + n];
        a0 += cs[k] * w;
        a1 += cs[1024 + k] * w;
        a2 += cs[2048 + k] * w;
        a3 += cs[3072 + k] * w;
    }
    float bb = bias[n];
    mod[n] = a0 + bb;
    mod[MODW + n] = a1 + bb;
    mod[2 * MODW + n] = a2 + bb;
    mod[3 * MODW + n] = a3 + bb;
}

// ---------------- K1: LayerNorm + modulate -----------------------------------
__global__ void ln_mod_kernel(const float* __restrict__ x,
                              const float* __restrict__ w,
                              const float* __restrict__ mod,
                              int shOff, int scOff,
                              float* __restrict__ out) {
    int token = blockIdx.x;
    int b = token >> 11;
    int tid = threadIdx.x;
    const float* xr = x + (size_t)token * DMODEL;
    float v[4];
    float lsum = 0.f, lsq = 0.f;
    #pragma unroll
    for (int i = 0; i < 4; i++) {
        v[i] = xr[i * 256 + tid];
        lsum += v[i];
        lsq  += v[i] * v[i];
    }
    __shared__ float s1[8], s2[8];
    float ws = warpSum(lsum), wq = warpSum(lsq);
    int warp = tid >> 5, lane = tid & 31;
    if (lane == 0) { s1[warp] = ws; s2[warp] = wq; }
    __syncthreads();
    __shared__ float s_mu, s_rstd;
    if (tid == 0) {
        float ts = 0.f, tq = 0.f;
        #pragma unroll
        for (int i = 0; i < 8; i++) { ts += s1[i]; tq += s2[i]; }
        float mu = ts * (1.0f / DMODEL);
        float var = tq * (1.0f / DMODEL) - mu * mu;
        s_mu = mu;
        s_rstd = rsqrtf(var + 1e-5f);
    }
    __syncthreads();
    float mu = s_mu, rstd = s_rstd;
    const float* mrow = mod + (size_t)b * MODW;
    float* orow = out + (size_t)token * DMODEL;
    #pragma unroll
    for (int i = 0; i < 4; i++) {
        int d = i * 256 + tid;
        float xn = (v[i] - mu) * rstd * w[d];
        orow[d] = xn * (1.f + mrow[scOff + d]) + mrow[shOff + d];
    }
}

// ---------------- K2: split-bf16 HMMA GEMM, 128x128 tile, K-chunk 32 ---------
// SMEM stage layout (bytes):
//   A_hi [128 rows x 40 halves (32 used)]  @ 0       size 10240  (row stride 80B)
//   A_lo                                   @ 10240   size 10240
//   B_hi [32 rows(k) x 136 halves (128)]   @ 20480   size 8704   (row stride 272B)
//   B_lo                                   @ 29184   size 8704
#define AST    80
#define BSTB   272
#define A_LO_OFF 10240
#define B_HI_OFF 20480
#define B_LO_OFF 29184
#define GEMM_SMEM 37888

template <int EPI>
__device__ __forceinline__ float epi_apply(float v, int m, int n, int N,
        const float* __restrict__ bias, const float* __restrict__ resid,
        const float* __restrict__ mod, int modOff) {
    if (EPI == 1) v = gelu_tanh(v + bias[n]);
    if (EPI == 2) v = resid[(size_t)m * N + n]
                    + mod[(size_t)(m >> 11) * MODW + modOff + n] * v;
    if (EPI == 3) v = resid[(size_t)m * N + n]
                    + mod[(size_t)(m >> 11) * MODW + modOff + n] * (v + bias[n]);
    return v;
}

// EPI 0: C = A@B
// EPI 1: C = gelu(A@B + bias)
// EPI 2: C = resid + mod[b, modOff+n] * (A@B)              (N == 1024)
// EPI 3: C = resid + mod[b, modOff+n] * (A@B + bias)       (N == 1024)
template <int EPI>
__global__ void __launch_bounds__(256, 2)
mma_gemm(const float* __restrict__ A, const float* __restrict__ B,
         float* __restrict__ C, int M, int N, int K,
         const float* __restrict__ bias,
         const float* __restrict__ resid,
         const float* __restrict__ mod, int modOff) {
    extern __shared__ char smem[];
    uint32_t sb = smem_u32(smem);
    int tid = threadIdx.x, lane = tid & 31, wid = tid >> 5;
    int wm = wid >> 1, wn = wid & 1;          // warp grid 4x2 -> 32x64 per warp
    int m0 = blockIdx.y * 128, n0 = blockIdx.x * 128;

    float acc[2][8][4];
    #pragma unroll
    for (int i = 0; i < 2; i++)
        #pragma unroll
        for (int j = 0; j < 8; j++)
            #pragma unroll
            for (int k = 0; k < 4; k++) acc[i][j][k] = 0.f;

    // STS indices
    int ar = tid >> 1, aseg = tid & 1;        // A: row, 16-col segment
    int bk = tid >> 3, bi = tid & 7;          // B: k row, col group

    // ldmatrix lane base addresses
    // A (non-trans x4): lanes 0-7 rows0-7 k0 | 8-15 rows8-15 k0 | 16-23 rows0-7 k8 | 24-31 rows8-15 k8
    uint32_t aBase = sb + (uint32_t)(wm * 32 + (lane & 15)) * AST + (uint32_t)((lane >> 4) * 8) * 2;
    // B (trans x4): group g = lane>>3: m0=(k0-7,n) m1=(k8-15,n) m2=(k0-7,n+8) m3=(k8-15,n+8)
    int bg = lane >> 3;
    uint32_t bBase = sb + B_HI_OFF
                   + (uint32_t)((bg & 1) * 8 + (lane & 7)) * BSTB
                   + (uint32_t)(wn * 64 + ((bg >> 1) & 1) * 8) * 2;

    const int nc = K >> 5;
    for (int c = 0; c < nc; c++) {
        int k0 = c << 5;
        // ---- gmem loads (regs) ----
        const float* Ag = A + (size_t)(m0 + ar) * K + k0 + aseg * 16;
        float4 av[4];
        #pragma unroll
        for (int i = 0; i < 4; i++) av[i] = *(const float4*)(Ag + i * 4);
        const float* Bg = B + (size_t)(k0 + bk) * N + n0;
        float4 bv[4];
        #pragma unroll
        for (int j = 0; j < 4; j++) bv[j] = *(const float4*)(Bg + (bi + j * 8) * 4);

        __syncthreads();   // previous mma phase done reading smem

        // ---- STS with split-bf16 conversion ----
        #pragma unroll
        for (int i = 0; i < 4; i++) {
            int col = aseg * 16 + i * 4;
            uint32_t lo0, lo1;
            uint32_t hi0 = split_pack(av[i].x, av[i].y, lo0);
            uint32_t hi1 = split_pack(av[i].z, av[i].w, lo1);
            uint32_t off = (uint32_t)ar * AST + col * 2;
            *(uint2*)(smem + off) = make_uint2(hi0, hi1);
            *(uint2*)(smem + A_LO_OFF + off) = make_uint2(lo0, lo1);
        }
        #pragma unroll
        for (int j = 0; j < 4; j++) {
            int col = (bi + j * 8) * 4;
            uint32_t lo0, lo1;
            uint32_t hi0 = split_pack(bv[j].x, bv[j].y, lo0);
            uint32_t hi1 = split_pack(bv[j].z, bv[j].w, lo1);
            uint32_t off = (uint32_t)bk * BSTB + col * 2;
            *(uint2*)(smem + B_HI_OFF + off) = make_uint2(hi0, hi1);
            *(uint2*)(smem + B_LO_OFF + off) = make_uint2(lo0, lo1);
        }
        __syncthreads();

        // ---- MMA phase: 2 k16 steps, 3 split passes ----
        #pragma unroll
        for (int ks = 0; ks < 2; ks++) {
            uint32_t ah[2][4], al[2][4];
            #pragma unroll
            for (int mt = 0; mt < 2; mt++) {
                ldsm4(ah[mt], aBase + mt * 16 * AST + ks * 32);
                ldsm4(al[mt], aBase + A_LO_OFF + mt * 16 * AST + ks * 32);
            }
            #pragma unroll
            for (int q = 0; q < 4; q++) {
                uint32_t bh[4], bl[4];
                ldsm4t(bh, bBase + q * 32 + ks * 16 * BSTB);
                ldsm4t(bl, bBase + (B_LO_OFF - B_HI_OFF) + q * 32 + ks * 16 * BSTB);
                #pragma unroll
                for (int mt = 0; mt < 2; mt++) {
                    mma16816(acc[mt][2 * q],     ah[mt], bh);
                    mma16816(acc[mt][2 * q],     ah[mt], bl);
                    mma16816(acc[mt][2 * q],     al[mt], bh);
                    mma16816(acc[mt][2 * q + 1], ah[mt], bh + 2);
                    mma16816(acc[mt][2 * q + 1], ah[mt], bl + 2);
                    mma16816(acc[mt][2 * q + 1], al[mt], bh + 2);
                }
            }
        }
    }

    // ---- epilogue: fragment regs -> gmem with fused ops ----
    int r0 = lane >> 2, cp = (lane & 3) * 2;
    #pragma unroll
    for (int mt = 0; mt < 2; mt++) {
        #pragma unroll
        for (int nt = 0; nt < 8; nt++) {
            int m = m0 + wm * 32 + mt * 16 + r0;
            int n = n0 + wn * 64 + nt * 8 + cp;
            float* cacc = acc[mt][nt];
            float2 o0, o1;
            o0.x = epi_apply<EPI>(cacc[0], m, n,     N, bias, resid, mod, modOff);
            o0.y = epi_apply<EPI>(cacc[1], m, n + 1, N, bias, resid, mod, modOff);
            o1.x = epi_apply<EPI>(cacc[2], m + 8, n,     N, bias, resid, mod, modOff);
            o1.y = epi_apply<EPI>(cacc[3], m + 8, n + 1, N, bias, resid, mod, modOff);
            *(float2*)&C[(size_t)m * N + n] = o0;
            *(float2*)&C[(size_t)(m + 8) * N + n] = o1;
        }
    }
}

// ---------------- K3: RMSNorm + RoPE on q,k ----------------------------------
__global__ void rope_kernel(float* __restrict__ qkv,
                            const float* __restrict__ cosb,
                            const float* __restrict__ sinb,
                            const float* __restrict__ qw,
                            const float* __restrict__ kw) {
    int gwid = blockIdx.x * 8 + (threadIdx.x >> 5);
    int lane = threadIdx.x & 31;
    int bs = gwid >> 5;
    int rem = gwid & 31;
    int h = rem >> 1;
    int t = rem & 1;
    float* base = qkv + (((size_t)bs * 3 + t) * NHEAD + h) * HDIM;
    const float* w = (t == 0) ? qw : kw;
    int s = bs & (SEQ - 1);
    float x0 = base[lane];
    float x1 = base[lane + 32];
    float ss = warpSum(x0 * x0 + x1 * x1);
    float rinv = rsqrtf(ss * (1.0f / HDIM) + 1e-6f);
    float n0 = x0 * rinv * w[lane];
    float n1 = x1 * rinv * w[lane + 32];
    const float* cr = cosb + (size_t)s * HDIM;
    const float* sr = sinb + (size_t)s * HDIM;
    float c0 = cr[lane], c1 = cr[lane + 32];
    float s0 = sr[lane], s1 = sr[lane + 32];
    base[lane]      = n0 * c0 - n1 * s0;
    base[lane + 32] = n1 * c1 + n0 * s1;
}

// ---------------- K4: flash-style attention (SIMT fp32) ----------------------
__global__ void flash_attn(const float* __restrict__ qkv, float* __restrict__ out) {
    extern __shared__ float sm[];
    float* Qs = sm;
    float* Ks = Qs + 64 * 65;
    float* Ss = Ks + 64 * 65;
    float* Vs = Ss + 64 * 65;
    float* mS = Vs + 64 * 64;
    float* lS = mS + 64;
    float* aS = lS + 64;

    int b = blockIdx.x >> 4, h = blockIdx.x & 15;
    int q0 = blockIdx.y * 64;
    int tid = threadIdx.x;

    for (int idx = tid; idx < 1024; idx += 256) {
        int r = idx >> 4, c = (idx & 15) * 4;
        const float* p = qkv + (((size_t)(b * SEQ + q0 + r) * 3 + 0) * NHEAD + h) * HDIM + c;
        float4 v = *(const float4*)p;
        Qs[r * 65 + c + 0] = v.x * 0.125f;
        Qs[r * 65 + c + 1] = v.y * 0.125f;
        Qs[r * 65 + c + 2] = v.z * 0.125f;
        Qs[r * 65 + c + 3] = v.w * 0.125f;
    }
    if (tid < 64) { mS[tid] = -1e30f; lS[tid] = 0.f; }

    float o[16];
    #pragma unroll
    for (int j = 0; j < 16; j++) o[j] = 0.f;
    int orow = tid & 63;
    int obase = (tid >> 6) * 16;
    int sr0 = (tid & 15) * 4;
    int sk0 = (tid >> 4) * 4;

    for (int kt = 0; kt < SEQ / 64; kt++) {
        __syncthreads();
        int k0 = kt * 64;
        for (int idx = tid; idx < 1024; idx += 256) {
            int r = idx >> 4, c = (idx & 15) * 4;
            const float* pk = qkv + (((size_t)(b * SEQ + k0 + r) * 3 + 1) * NHEAD + h) * HDIM + c;
            const float* pv = qkv + (((size_t)(b * SEQ + k0 + r) * 3 + 2) * NHEAD + h) * HDIM + c;
            float4 kv = *(const float4*)pk;
            Ks[r * 65 + c + 0] = kv.x;
            Ks[r * 65 + c + 1] = kv.y;
            Ks[r * 65 + c + 2] = kv.z;
            Ks[r * 65 + c + 3] = kv.w;
            *(float4*)&Vs[r * 64 + c] = *(const float4*)pv;
        }
        __syncthreads();

        float sacc[4][4];
        #pragma unroll
        for (int i = 0; i < 4; i++)
            #pragma unroll
            for (int j = 0; j < 4; j++) sacc[i][j] = 0.f;
        #pragma unroll 4
        for (int d = 0; d < 64; d++) {
            float qa[4], kb[4];
            #pragma unroll
            for (int i = 0; i < 4; i++) qa[i] = Qs[(sr0 + i) * 65 + d];
            #pragma unroll
            for (int j = 0; j < 4; j++) kb[j] = Ks[(sk0 + j) * 65 + d];
            #pragma unroll
            for (int i = 0; i < 4; i++)
                #pragma unroll
                for (int j = 0; j < 4; j++)
                    sacc[i][j] = fmaf(qa[i], kb[j], sacc[i][j]);
        }
        #pragma unroll
        for (int i = 0; i < 4; i++)
            #pragma unroll
            for (int j = 0; j < 4; j++)
                Ss[(sr0 + i) * 65 + sk0 + j] = sacc[i][j];
        __syncthreads();

        if (tid < 64) {
            int r = tid;
            float mold = mS[r], mnew = mold;
            #pragma unroll 8
            for (int kk = 0; kk < 64; kk++) mnew = fmaxf(mnew, Ss[r * 65 + kk]);
            float alpha = __expf(mold - mnew);
            float ls = 0.f;
            #pragma unroll 8
            for (int kk = 0; kk < 64; kk++) {
                float e = __expf(Ss[r * 65 + kk] - mnew);
                Ss[r * 65 + kk] = e;
                ls += e;
            }
            mS[r] = mnew;
            lS[r] = lS[r] * alpha + ls;
            aS[r] = alpha;
        }
        __syncthreads();

        float al = aS[orow];
        #pragma unroll
        for (int j = 0; j < 16; j++) o[j] *= al;
        #pragma unroll 4
        for (int kk = 0; kk < 64; kk++) {
            float p = Ss[orow * 65 + kk];
            const float4* vp = (const float4*)&Vs[kk * 64 + obase];
            float4 v0 = vp[0], v1 = vp[1], v2 = vp[2], v3 = vp[3];
            o[0]  = fmaf(p, v0.x, o[0]);   o[1]  = fmaf(p, v0.y, o[1]);
            o[2]  = fmaf(p, v0.z, o[2]);   o[3]  = fmaf(p, v0.w, o[3]);
            o[4]  = fmaf(p, v1.x, o[4]);   o[5]  = fmaf(p, v1.y, o[5]);
            o[6]  = fmaf(p, v1.z, o[6]);   o[7]  = fmaf(p, v1.w, o[7]);
            o[8]  = fmaf(p, v2.x, o[8]);   o[9]  = fmaf(p, v2.y, o[9]);
            o[10] = fmaf(p, v2.z, o[10]);  o[11] = fmaf(p, v2.w, o[11]);
            o[12] = fmaf(p, v3.x, o[12]);  o[13] = fmaf(p, v3.y, o[13]);
            o[14] = fmaf(p, v3.z, o[14]);  o[15] = fmaf(p, v3.w, o[15]);
        }
    }

    float inv = 1.f / lS[orow];
    float* op = out + (size_t)(b * SEQ + q0 + orow) * DMODEL + h * HDIM + obase;
    #pragma unroll
    for (int j = 0; j < 16; j++) op[j] = o[j] * inv;
}

// ---------------- launcher ---------------------------------------------------
extern "C" void kernel_launch(void* const* d_in, const int* in_sizes, int n_in,
                              void* d_out, int out_size) {
    const float* x       = (const float*)d_in[0];
    const float* cosb    = (const float*)d_in[1];
    const float* sinb    = (const float*)d_in[2];
    const float* c       = (const float*)d_in[3];
    const float* norm1_w = (const float*)d_in[4];
    const float* Wqkv    = (const float*)d_in[5];
    const float* Wout    = (const float*)d_in[6];
    const float* q_norm_w= (const float*)d_in[7];
    const float* k_norm_w= (const float*)d_in[8];
    const float* norm2_w = (const float*)d_in[9];
    const float* W1      = (const float*)d_in[10];
    const float* b1      = (const float*)d_in[11];
    const float* W2      = (const float*)d_in[12];
    const float* b2      = (const float*)d_in[13];
    const float* ada_W   = (const float*)d_in[14];
    const float* ada_b   = (const float*)d_in[15];
    float* out = (float*)d_out;

    float *mod_p, *xn_p, *qkv_p, *attn_p, *h_p;
    cudaGetSymbolAddress((void**)&mod_p, g_mod);
    cudaGetSymbolAddress((void**)&xn_p, g_xn);
    cudaGetSymbolAddress((void**)&qkv_p, g_qkv);
    cudaGetSymbolAddress((void**)&attn_p, g_attn);
    cudaGetSymbolAddress((void**)&h_p, g_h);

    // K0: modulation
    ada_kernel<<<MODW / 256, 256>>>(c, ada_W, ada_b, mod_p);

    // K1: LN1 + modulate (sh_msa @0, sc_msa @1024)
    ln_mod_kernel<<<TOKENS, 256>>>(x, norm1_w, mod_p, 0, 1024, xn_p);

    // K2: QKV GEMM (8192 x 3072 x 1024)
    mma_gemm<0><<<dim3(3 * DMODEL / 128, TOKENS / 128), 256, GEMM_SMEM>>>(
        xn_p, Wqkv, qkv_p, TOKENS, 3 * DMODEL, DMODEL, nullptr, nullptr, nullptr, 0);

    // K3: RMSNorm + RoPE on q,k
    rope_kernel<<<TOKENS * NHEAD * 2 / 8, 256>>>(qkv_p, cosb, sinb, q_norm_w, k_norm_w);

    // K4: attention
    int smem = (3 * 64 * 65 + 64 * 64 + 3 * 64) * sizeof(float);  // 67072 B
    cudaFuncSetAttribute(flash_attn, cudaFuncAttributeMaxDynamicSharedMemorySize, smem);
    flash_attn<<<dim3(BATCH * NHEAD, SEQ / 64), 256, smem>>>(qkv_p, attn_p);

    // K5: Wout GEMM + gated residual (g_msa @2048)
    mma_gemm<2><<<dim3(DMODEL / 128, TOKENS / 128), 256, GEMM_SMEM>>>(
        attn_p, Wout, out, TOKENS, DMODEL, DMODEL, nullptr, x, mod_p, 2048);

    // K6: LN2 + modulate (sh_mlp @3072, sc_mlp @4096)
    ln_mod_kernel<<<TOKENS, 256>>>(out, norm2_w, mod_p, 3072, 4096, xn_p);

    // K7: MLP up GEMM + bias + gelu
    mma_gemm<1><<<dim3(DFF / 128, TOKENS / 128), 256, GEMM_SMEM>>>(
        xn_p, W1, h_p, TOKENS, DFF, DMODEL, b1, nullptr, nullptr, 0);

    // K8: MLP down GEMM + bias + gated residual (g_mlp @5120), in-place on d_out
    mma_gemm<3><<<dim3(DMODEL / 128, TOKENS / 128), 256, GEMM_SMEM>>>(
        h_p, W2, out, TOKENS, DMODEL, DFF, b2, out, mod_p, 5120);
}

// round 11
// speedup vs baseline: 1.6638x; 1.5732x over previous
#include <cuda_runtime.h>
#include <cuda_bf16.h>
#include <math.h>
#include <stdint.h>

// Problem constants
#define BATCH 4
#define SEQ   2048
#define DMODEL 1024
#define NHEAD 16
#define HDIM  64
#define DFF   4096
#define TOKENS (BATCH*SEQ)       // 8192
#define MODW  6144               // 6*D

// ---------------- scratch (device globals; no allocations allowed) ----------
__device__ float g_mod[BATCH * MODW];
__device__ float g_qkv[(size_t)TOKENS * 3 * DMODEL];
__device__ __nv_bfloat16 g_xn_hi[(size_t)TOKENS * DMODEL];
__device__ __nv_bfloat16 g_xn_lo[(size_t)TOKENS * DMODEL];
__device__ __nv_bfloat16 g_attn_hi[(size_t)TOKENS * DMODEL];
__device__ __nv_bfloat16 g_attn_lo[(size_t)TOKENS * DMODEL];
__device__ __nv_bfloat16 g_h_hi[(size_t)TOKENS * DFF];
__device__ __nv_bfloat16 g_h_lo[(size_t)TOKENS * DFF];
__device__ __nv_bfloat16 g_wqkv_hi[(size_t)DMODEL * 3 * DMODEL];
__device__ __nv_bfloat16 g_wqkv_lo[(size_t)DMODEL * 3 * DMODEL];
__device__ __nv_bfloat16 g_wout_hi[(size_t)DMODEL * DMODEL];
__device__ __nv_bfloat16 g_wout_lo[(size_t)DMODEL * DMODEL];
__device__ __nv_bfloat16 g_w1_hi[(size_t)DMODEL * DFF];
__device__ __nv_bfloat16 g_w1_lo[(size_t)DMODEL * DFF];
__device__ __nv_bfloat16 g_w2_hi[(size_t)DFF * DMODEL];
__device__ __nv_bfloat16 g_w2_lo[(size_t)DFF * DMODEL];

// ---------------- generic helpers -------------------------------------------
__device__ __forceinline__ float warpSum(float v) {
    v += __shfl_xor_sync(0xffffffffu, v, 16);
    v += __shfl_xor_sync(0xffffffffu, v, 8);
    v += __shfl_xor_sync(0xffffffffu, v, 4);
    v += __shfl_xor_sync(0xffffffffu, v, 2);
    v += __shfl_xor_sync(0xffffffffu, v, 1);
    return v;
}

__device__ __forceinline__ float gelu_tanh(float x) {
    float x3 = x * x * x;
    return 0.5f * x * (1.0f + tanhf(0.7978845608028654f * (x + 0.044715f * x3)));
}

__device__ __forceinline__ uint32_t smem_u32(const void* p) {
    uint32_t a;
    asm("{ .reg .u64 t; cvta.to.shared.u64 t, %1; cvt.u32.u64 %0, t; }" : "=r"(a) : "l"(p));
    return a;
}

// fp32 -> (hi, lo) bf16 pair, packed two-at-a-time into b32 (a in low half)
__device__ __forceinline__ uint32_t split_pack(float a, float b, uint32_t& lo) {
    __nv_bfloat16 ha = __float2bfloat16(a), hb = __float2bfloat16(b);
    float ra = a - __bfloat162float(ha);
    float rb = b - __bfloat162float(hb);
    __nv_bfloat16 la = __float2bfloat16(ra), lb = __float2bfloat16(rb);
    lo = (uint32_t)__bfloat16_as_ushort(la) | ((uint32_t)__bfloat16_as_ushort(lb) << 16);
    return (uint32_t)__bfloat16_as_ushort(ha) | ((uint32_t)__bfloat16_as_ushort(hb) << 16);
}

__device__ __forceinline__ void split_store1(__nv_bfloat16* hi, __nv_bfloat16* lo,
                                             size_t idx, float v) {
    __nv_bfloat16 h = __float2bfloat16(v);
    hi[idx] = h;
    lo[idx] = __float2bfloat16(v - __bfloat162float(h));
}

__device__ __forceinline__ void split_store2(__nv_bfloat16* hi, __nv_bfloat16* lo,
                                             size_t idx, float a, float b) {
    __nv_bfloat16 ha = __float2bfloat16(a), hb = __float2bfloat16(b);
    __nv_bfloat162 hv; hv.x = ha; hv.y = hb;
    *(__nv_bfloat162*)&hi[idx] = hv;
    __nv_bfloat162 lv;
    lv.x = __float2bfloat16(a - __bfloat162float(ha));
    lv.y = __float2bfloat16(b - __bfloat162float(hb));
    *(__nv_bfloat162*)&lo[idx] = lv;
}

// ---------------- warp-level MMA primitives (sm_80+, no 'a' features) --------
__device__ __forceinline__ void ldsm4(uint32_t* r, uint32_t a) {
    asm volatile("ldmatrix.sync.aligned.m8n8.x4.shared.b16 {%0,%1,%2,%3}, [%4];"
        : "=r"(r[0]), "=r"(r[1]), "=r"(r[2]), "=r"(r[3]) : "r"(a));
}
__device__ __forceinline__ void ldsm4t(uint32_t* r, uint32_t a) {
    asm volatile("ldmatrix.sync.aligned.m8n8.x4.trans.shared.b16 {%0,%1,%2,%3}, [%4];"
        : "=r"(r[0]), "=r"(r[1]), "=r"(r[2]), "=r"(r[3]) : "r"(a));
}
__device__ __forceinline__ void mma16816(float* c, const uint32_t* a, const uint32_t* b) {
    asm volatile(
        "mma.sync.aligned.m16n8k16.row.col.f32.bf16.bf16.f32 "
        "{%0,%1,%2,%3}, {%4,%5,%6,%7}, {%8,%9}, {%0,%1,%2,%3};"
        : "+f"(c[0]), "+f"(c[1]), "+f"(c[2]), "+f"(c[3])
        : "r"(a[0]), "r"(a[1]), "r"(a[2]), "r"(a[3]), "r"(b[0]), "r"(b[1]));
}

__device__ __forceinline__ void cpa16(uint32_t s, const void* g) {
    asm volatile("cp.async.cg.shared.global [%0], [%1], 16;" :: "r"(s), "l"(g));
}
#define CP_COMMIT() asm volatile("cp.async.commit_group;" ::: "memory")
#define CP_WAIT1()  asm volatile("cp.async.wait_group 1;" ::: "memory")
#define CP_WAIT0()  asm volatile("cp.async.wait_group 0;" ::: "memory")

// ---------------- K-1: weight pre-split (fp32 -> bf16 hi/lo planes) ----------
__global__ void split_w(const float* __restrict__ W,
                        __nv_bfloat16* __restrict__ hi,
                        __nv_bfloat16* __restrict__ lo, int n4) {
    int i = blockIdx.x * 256 + threadIdx.x;
    if (i >= n4) return;
    float4 v = ((const float4*)W)[i];
    uint32_t l0, l1;
    uint32_t h0 = split_pack(v.x, v.y, l0);
    uint32_t h1 = split_pack(v.z, v.w, l1);
    ((uint2*)hi)[i] = make_uint2(h0, h1);
    ((uint2*)lo)[i] = make_uint2(l0, l1);
}

// ---------------- K0: adaLN modulation ---------------------------------------
__global__ void ada_kernel(const float* __restrict__ c,
                           const float* __restrict__ W,
                           const float* __restrict__ bias,
                           float* __restrict__ mod) {
    __shared__ float cs[BATCH * 1024];
    int tid = threadIdx.x;
    for (int i = tid; i < BATCH * 1024; i += 256) cs[i] = c[i];
    __syncthreads();
    int n = blockIdx.x * 256 + tid;
    float a0 = 0.f, a1 = 0.f, a2 = 0.f, a3 = 0.f;
    #pragma unroll 4
    for (int k = 0; k < 1024; k++) {
        float w = W[(size_t)k * MODW + n];
        a0 += cs[k] * w;
        a1 += cs[1024 + k] * w;
        a2 += cs[2048 + k] * w;
        a3 += cs[3072 + k] * w;
    }
    float bb = bias[n];
    mod[n] = a0 + bb;
    mod[MODW + n] = a1 + bb;
    mod[2 * MODW + n] = a2 + bb;
    mod[3 * MODW + n] = a3 + bb;
}

// ---------------- K1: LayerNorm + modulate -> split bf16 planes --------------
__global__ void ln_mod_kernel(const float* __restrict__ x,
                              const float* __restrict__ w,
                              const float* __restrict__ mod,
                              int shOff, int scOff,
                              __nv_bfloat16* __restrict__ ohi,
                              __nv_bfloat16* __restrict__ olo) {
    int token = blockIdx.x;
    int b = token >> 11;
    int tid = threadIdx.x;
    const float* xr = x + (size_t)token * DMODEL;
    float v[4];
    float lsum = 0.f, lsq = 0.f;
    #pragma unroll
    for (int i = 0; i < 4; i++) {
        v[i] = xr[i * 256 + tid];
        lsum += v[i];
        lsq  += v[i] * v[i];
    }
    __shared__ float s1[8], s2[8];
    float ws = warpSum(lsum), wq = warpSum(lsq);
    int warp = tid >> 5, lane = tid & 31;
    if (lane == 0) { s1[warp] = ws; s2[warp] = wq; }
    __syncthreads();
    __shared__ float s_mu, s_rstd;
    if (tid == 0) {
        float ts = 0.f, tq = 0.f;
        #pragma unroll
        for (int i = 0; i < 8; i++) { ts += s1[i]; tq += s2[i]; }
        float mu = ts * (1.0f / DMODEL);
        float var = tq * (1.0f / DMODEL) - mu * mu;
        s_mu = mu;
        s_rstd = rsqrtf(var + 1e-5f);
    }
    __syncthreads();
    float mu = s_mu, rstd = s_rstd;
    const float* mrow = mod + (size_t)b * MODW;
    size_t rowoff = (size_t)token * DMODEL;
    #pragma unroll
    for (int i = 0; i < 4; i++) {
        int d = i * 256 + tid;
        float xn = (v[i] - mu) * rstd * w[d];
        float val = xn * (1.f + mrow[scOff + d]) + mrow[shOff + d];
        split_store1(ohi, olo, rowoff + d, val);
    }
}

// ---------------- K2: split-bf16 HMMA GEMM, cp.async double-buffered ---------
// Stage layout (bytes):
//   A_hi [128 rows x 32 halves, stride 80]   @ 0       10240
//   A_lo                                     @ 10240   10240
//   B_hi [32 k-rows x 128 halves, stride 272]@ 20480   8704
//   B_lo                                     @ 29184   8704
#define AST    80
#define BSTB   272
#define A_LO_OFF 10240
#define B_HI_OFF 20480
#define STAGE  37888
#define GEMM_SMEM (2 * STAGE)   // 75776

template <int EPI>
__device__ __forceinline__ float epi_apply(float v, int m, int n, int N,
        const float* __restrict__ bias, const float* __restrict__ resid,
        const float* __restrict__ mod, int modOff) {
    if (EPI == 2) v = resid[(size_t)m * N + n]
                    + mod[(size_t)(m >> 11) * MODW + modOff + n] * v;
    if (EPI == 3) v = resid[(size_t)m * N + n]
                    + mod[(size_t)(m >> 11) * MODW + modOff + n] * (v + bias[n]);
    return v;
}

// EPI 0: C(fp32) = A@B
// EPI 1: Chi/Clo(bf16 split) = gelu(A@B + bias)
// EPI 2: C = resid + mod[b, modOff+n] * (A@B)              (N == 1024)
// EPI 3: C = resid + mod[b, modOff+n] * (A@B + bias)       (N == 1024)
template <int EPI>
__global__ void __launch_bounds__(256, 2)
mma_gemm(const __nv_bfloat16* __restrict__ Ahg, const __nv_bfloat16* __restrict__ Alg,
         const __nv_bfloat16* __restrict__ Bhg, const __nv_bfloat16* __restrict__ Blg,
         float* __restrict__ C,
         __nv_bfloat16* __restrict__ Chi, __nv_bfloat16* __restrict__ Clo,
         int M, int N, int K,
         const float* __restrict__ bias,
         const float* __restrict__ resid,
         const float* __restrict__ mod, int modOff) {
    extern __shared__ char smem[];
    uint32_t sb = smem_u32(smem);
    int tid = threadIdx.x, lane = tid & 31, wid = tid >> 5;
    int wm = wid >> 1, wn = wid & 1;          // warp grid 4x2 -> 32x64 per warp
    int m0 = blockIdx.y * 128, n0 = blockIdx.x * 128;

    float acc[2][8][4];
    #pragma unroll
    for (int i = 0; i < 2; i++)
        #pragma unroll
        for (int j = 0; j < 8; j++)
            #pragma unroll
            for (int k = 0; k < 4; k++) acc[i][j][k] = 0.f;

    // cp.async segment indices (each thread: 2 segs per plane)
    int s0 = tid * 2;
    int arow0 = s0 >> 2,  aoff0 = s0 & 3;
    int arow1 = (s0+1) >> 2, aoff1 = (s0+1) & 3;
    int brow0 = s0 >> 4,  boff0 = s0 & 15;
    int brow1 = (s0+1) >> 4, boff1 = (s0+1) & 15;

    // ldmatrix lane base addresses (verified mapping)
    uint32_t aBase = sb + (uint32_t)(wm * 32 + (lane & 15)) * AST + (uint32_t)((lane >> 4) * 8) * 2;
    int bg = lane >> 3;
    uint32_t bBase = sb + B_HI_OFF
                   + (uint32_t)((bg & 1) * 8 + (lane & 7)) * BSTB
                   + (uint32_t)(wn * 64 + ((bg >> 1) & 1) * 8) * 2;

    const int nc = K >> 5;

    auto load_stage = [&](int c, int st) {
        int k0 = c << 5;
        uint32_t sA = sb + st * STAGE;
        uint32_t sB = sA + B_HI_OFF;
        // A planes
        const __nv_bfloat16* g;
        uint32_t d;
        g = Ahg + (size_t)(m0 + arow0) * K + k0 + aoff0 * 8;
        d = sA + arow0 * AST + aoff0 * 16;
        cpa16(d, g);
        g = Alg + (size_t)(m0 + arow0) * K + k0 + aoff0 * 8;
        cpa16(d + A_LO_OFF, g);
        g = Ahg + (size_t)(m0 + arow1) * K + k0 + aoff1 * 8;
        d = sA + arow1 * AST + aoff1 * 16;
        cpa16(d, g);
        g = Alg + (size_t)(m0 + arow1) * K + k0 + aoff1 * 8;
        cpa16(d + A_LO_OFF, g);
        // B planes
        g = Bhg + (size_t)(k0 + brow0) * N + n0 + boff0 * 8;
        d = sB + brow0 * BSTB + boff0 * 16;
        cpa16(d, g);
        g = Blg + (size_t)(k0 + brow0) * N + n0 + boff0 * 8;
        cpa16(d + 8704, g);
        g = Bhg + (size_t)(k0 + brow1) * N + n0 + boff1 * 8;
        d = sB + brow1 * BSTB + boff1 * 16;
        cpa16(d, g);
        g = Blg + (size_t)(k0 + brow1) * N + n0 + boff1 * 8;
        cpa16(d + 8704, g);
    };

    load_stage(0, 0);
    CP_COMMIT();

    for (int c = 0; c < nc; c++) {
        if (c + 1 < nc) {
            load_stage(c + 1, (c + 1) & 1);
            CP_COMMIT();
            CP_WAIT1();
        } else {
            CP_WAIT0();
        }
        __syncthreads();

        uint32_t stOff = (uint32_t)(c & 1) * STAGE;
        #pragma unroll
        for (int ks = 0; ks < 2; ks++) {
            uint32_t ah[2][4], al[2][4];
            #pragma unroll
            for (int mt = 0; mt < 2; mt++) {
                ldsm4(ah[mt], aBase + stOff + mt * 16 * AST + ks * 32);
                ldsm4(al[mt], aBase + stOff + A_LO_OFF + mt * 16 * AST + ks * 32);
            }
            #pragma unroll
            for (int q = 0; q < 4; q++) {
                uint32_t bh[4], bl[4];
                ldsm4t(bh, bBase + stOff + q * 32 + ks * 16 * BSTB);
                ldsm4t(bl, bBase + stOff + 8704 + q * 32 + ks * 16 * BSTB);
                #pragma unroll
                for (int mt = 0; mt < 2; mt++) {
                    mma16816(acc[mt][2 * q],     ah[mt], bh);
                    mma16816(acc[mt][2 * q],     ah[mt], bl);
                    mma16816(acc[mt][2 * q],     al[mt], bh);
                    mma16816(acc[mt][2 * q + 1], ah[mt], bh + 2);
                    mma16816(acc[mt][2 * q + 1], ah[mt], bl + 2);
                    mma16816(acc[mt][2 * q + 1], al[mt], bh + 2);
                }
            }
        }
        __syncthreads();
    }

    // ---- epilogue: fragment regs -> gmem with fused ops ----
    int r0 = lane >> 2, cp2 = (lane & 3) * 2;
    #pragma unroll
    for (int mt = 0; mt < 2; mt++) {
        #pragma unroll
        for (int nt = 0; nt < 8; nt++) {
            int m = m0 + wm * 32 + mt * 16 + r0;
            int n = n0 + wn * 64 + nt * 8 + cp2;
            float* cacc = acc[mt][nt];
            if (EPI == 1) {
                float v00 = gelu_tanh(cacc[0] + bias[n]);
                float v01 = gelu_tanh(cacc[1] + bias[n + 1]);
                float v10 = gelu_tanh(cacc[2] + bias[n]);
                float v11 = gelu_tanh(cacc[3] + bias[n + 1]);
                split_store2(Chi, Clo, (size_t)m * N + n, v00, v01);
                split_store2(Chi, Clo, (size_t)(m + 8) * N + n, v10, v11);
            } else {
                float2 o0, o1;
                o0.x = epi_apply<EPI>(cacc[0], m, n,     N, bias, resid, mod, modOff);
                o0.y = epi_apply<EPI>(cacc[1], m, n + 1, N, bias, resid, mod, modOff);
                o1.x = epi_apply<EPI>(cacc[2], m + 8, n,     N, bias, resid, mod, modOff);
                o1.y = epi_apply<EPI>(cacc[3], m + 8, n + 1, N, bias, resid, mod, modOff);
                *(float2*)&C[(size_t)m * N + n] = o0;
                *(float2*)&C[(size_t)(m + 8) * N + n] = o1;
            }
        }
    }
}

// ---------------- K3: RMSNorm + RoPE on q,k (fp32 qkv in-place) --------------
__global__ void rope_kernel(float* __restrict__ qkv,
                            const float* __restrict__ cosb,
                            const float* __restrict__ sinb,
                            const float* __restrict__ qw,
                            const float* __restrict__ kw) {
    int gwid = blockIdx.x * 8 + (threadIdx.x >> 5);
    int lane = threadIdx.x & 31;
    int bs = gwid >> 5;
    int rem = gwid & 31;
    int h = rem >> 1;
    int t = rem & 1;
    float* base = qkv + (((size_t)bs * 3 + t) * NHEAD + h) * HDIM;
    const float* w = (t == 0) ? qw : kw;
    int s = bs & (SEQ - 1);
    float x0 = base[lane];
    float x1 = base[lane + 32];
    float ss = warpSum(x0 * x0 + x1 * x1);
    float rinv = rsqrtf(ss * (1.0f / HDIM) + 1e-6f);
    float n0 = x0 * rinv * w[lane];
    float n1 = x1 * rinv * w[lane + 32];
    const float* cr = cosb + (size_t)s * HDIM;
    const float* sr = sinb + (size_t)s * HDIM;
    float c0 = cr[lane], c1 = cr[lane + 32];
    float s0 = sr[lane], s1 = sr[lane + 32];
    base[lane]      = n0 * c0 - n1 * s0;
    base[lane + 32] = n1 * c1 + n0 * s1;
}

// ---------------- K4: flash-style attention (SIMT fp32) -> split output ------
__global__ void flash_attn(const float* __restrict__ qkv,
                           __nv_bfloat16* __restrict__ ohi,
                           __nv_bfloat16* __restrict__ olo) {
    extern __shared__ float sm[];
    float* Qs = sm;
    float* Ks = Qs + 64 * 65;
    float* Ss = Ks + 64 * 65;
    float* Vs = Ss + 64 * 65;
    float* mS = Vs + 64 * 64;
    float* lS = mS + 64;
    float* aS = lS + 64;

    int b = blockIdx.x >> 4, h = blockIdx.x & 15;
    int q0 = blockIdx.y * 64;
    int tid = threadIdx.x;

    for (int idx = tid; idx < 1024; idx += 256) {
        int r = idx >> 4, c = (idx & 15) * 4;
        const float* p = qkv + (((size_t)(b * SEQ + q0 + r) * 3 + 0) * NHEAD + h) * HDIM + c;
        float4 v = *(const float4*)p;
        Qs[r * 65 + c + 0] = v.x * 0.125f;
        Qs[r * 65 + c + 1] = v.y * 0.125f;
        Qs[r * 65 + c + 2] = v.z * 0.125f;
        Qs[r * 65 + c + 3] = v.w * 0.125f;
    }
    if (tid < 64) { mS[tid] = -1e30f; lS[tid] = 0.f; }

    float o[16];
    #pragma unroll
    for (int j = 0; j < 16; j++) o[j] = 0.f;
    int orow = tid & 63;
    int obase = (tid >> 6) * 16;
    int sr0 = (tid & 15) * 4;
    int sk0 = (tid >> 4) * 4;

    for (int kt = 0; kt < SEQ / 64; kt++) {
        __syncthreads();
        int k0 = kt * 64;
        for (int idx = tid; idx < 1024; idx += 256) {
            int r = idx >> 4, c = (idx & 15) * 4;
            const float* pk = qkv + (((size_t)(b * SEQ + k0 + r) * 3 + 1) * NHEAD + h) * HDIM + c;
            const float* pv = qkv + (((size_t)(b * SEQ + k0 + r) * 3 + 2) * NHEAD + h) * HDIM + c;
            float4 kv = *(const float4*)pk;
            Ks[r * 65 + c + 0] = kv.x;
            Ks[r * 65 + c + 1] = kv.y;
            Ks[r * 65 + c + 2] = kv.z;
            Ks[r * 65 + c + 3] = kv.w;
            *(float4*)&Vs[r * 64 + c] = *(const float4*)pv;
        }
        __syncthreads();

        float sacc[4][4];
        #pragma unroll
        for (int i = 0; i < 4; i++)
            #pragma unroll
            for (int j = 0; j < 4; j++) sacc[i][j] = 0.f;
        #pragma unroll 4
        for (int d = 0; d < 64; d++) {
            float qa[4], kb[4];
            #pragma unroll
            for (int i = 0; i < 4; i++) qa[i] = Qs[(sr0 + i) * 65 + d];
            #pragma unroll
            for (int j = 0; j < 4; j++) kb[j] = Ks[(sk0 + j) * 65 + d];
            #pragma unroll
            for (int i = 0; i < 4; i++)
                #pragma unroll
                for (int j = 0; j < 4; j++)
                    sacc[i][j] = fmaf(qa[i], kb[j], sacc[i][j]);
        }
        #pragma unroll
        for (int i = 0; i < 4; i++)
            #pragma unroll
            for (int j = 0; j < 4; j++)
                Ss[(sr0 + i) * 65 + sk0 + j] = sacc[i][j];
        __syncthreads();

        if (tid < 64) {
            int r = tid;
            float mold = mS[r], mnew = mold;
            #pragma unroll 8
            for (int kk = 0; kk < 64; kk++) mnew = fmaxf(mnew, Ss[r * 65 + kk]);
            float alpha = __expf(mold - mnew);
            float ls = 0.f;
            #pragma unroll 8
            for (int kk = 0; kk < 64; kk++) {
                float e = __expf(Ss[r * 65 + kk] - mnew);
                Ss[r * 65 + kk] = e;
                ls += e;
            }
            mS[r] = mnew;
            lS[r] = lS[r] * alpha + ls;
            aS[r] = alpha;
        }
        __syncthreads();

        float al = aS[orow];
        #pragma unroll
        for (int j = 0; j < 16; j++) o[j] *= al;
        #pragma unroll 4
        for (int kk = 0; kk < 64; kk++) {
            float p = Ss[orow * 65 + kk];
            const float4* vp = (const float4*)&Vs[kk * 64 + obase];
            float4 v0 = vp[0], v1 = vp[1], v2 = vp[2], v3 = vp[3];
            o[0]  = fmaf(p, v0.x, o[0]);   o[1]  = fmaf(p, v0.y, o[1]);
            o[2]  = fmaf(p, v0.z, o[2]);   o[3]  = fmaf(p, v0.w, o[3]);
            o[4]  = fmaf(p, v1.x, o[4]);   o[5]  = fmaf(p, v1.y, o[5]);
            o[6]  = fmaf(p, v1.z, o[6]);   o[7]  = fmaf(p, v1.w, o[7]);
            o[8]  = fmaf(p, v2.x, o[8]);   o[9]  = fmaf(p, v2.y, o[9]);
            o[10] = fmaf(p, v2.z, o[10]);  o[11] = fmaf(p, v2.w, o[11]);
            o[12] = fmaf(p, v3.x, o[12]);  o[13] = fmaf(p, v3.y, o[13]);
            o[14] = fmaf(p, v3.z, o[14]);  o[15] = fmaf(p, v3.w, o[15]);
        }
    }

    float inv = 1.f / lS[orow];
    size_t base = (size_t)(b * SEQ + q0 + orow) * DMODEL + h * HDIM + obase;
    #pragma unroll
    for (int j = 0; j < 16; j += 2)
        split_store2(ohi, olo, base + j, o[j] * inv, o[j + 1] * inv);
}

// ---------------- launcher ---------------------------------------------------
extern "C" void kernel_launch(void* const* d_in, const int* in_sizes, int n_in,
                              void* d_out, int out_size) {
    const float* x       = (const float*)d_in[0];
    const float* cosb    = (const float*)d_in[1];
    const float* sinb    = (const float*)d_in[2];
    const float* c       = (const float*)d_in[3];
    const float* norm1_w = (const float*)d_in[4];
    const float* Wqkv    = (const float*)d_in[5];
    const float* Wout    = (const float*)d_in[6];
    const float* q_norm_w= (const float*)d_in[7];
    const float* k_norm_w= (const float*)d_in[8];
    const float* norm2_w = (const float*)d_in[9];
    const float* W1      = (const float*)d_in[10];
    const float* b1      = (const float*)d_in[11];
    const float* W2      = (const float*)d_in[12];
    const float* b2      = (const float*)d_in[13];
    const float* ada_W   = (const float*)d_in[14];
    const float* ada_b   = (const float*)d_in[15];
    float* out = (float*)d_out;

    float *mod_p, *qkv_p;
    __nv_bfloat16 *xnh, *xnl, *ath, *atl, *hh, *hl;
    __nv_bfloat16 *wqh, *wql, *woh, *wol, *w1h, *w1l, *w2h, *w2l;
    cudaGetSymbolAddress((void**)&mod_p, g_mod);
    cudaGetSymbolAddress((void**)&qkv_p, g_qkv);
    cudaGetSymbolAddress((void**)&xnh, g_xn_hi);
    cudaGetSymbolAddress((void**)&xnl, g_xn_lo);
    cudaGetSymbolAddress((void**)&ath, g_attn_hi);
    cudaGetSymbolAddress((void**)&atl, g_attn_lo);
    cudaGetSymbolAddress((void**)&hh, g_h_hi);
    cudaGetSymbolAddress((void**)&hl, g_h_lo);
    cudaGetSymbolAddress((void**)&wqh, g_wqkv_hi);
    cudaGetSymbolAddress((void**)&wql, g_wqkv_lo);
    cudaGetSymbolAddress((void**)&woh, g_wout_hi);
    cudaGetSymbolAddress((void**)&wol, g_wout_lo);
    cudaGetSymbolAddress((void**)&w1h, g_w1_hi);
    cudaGetSymbolAddress((void**)&w1l, g_w1_lo);
    cudaGetSymbolAddress((void**)&w2h, g_w2_hi);
    cudaGetSymbolAddress((void**)&w2l, g_w2_lo);

    cudaFuncSetAttribute(mma_gemm<0>, cudaFuncAttributeMaxDynamicSharedMemorySize, GEMM_SMEM);
    cudaFuncSetAttribute(mma_gemm<1>, cudaFuncAttributeMaxDynamicSharedMemorySize, GEMM_SMEM);
    cudaFuncSetAttribute(mma_gemm<2>, cudaFuncAttributeMaxDynamicSharedMemorySize, GEMM_SMEM);
    cudaFuncSetAttribute(mma_gemm<3>, cudaFuncAttributeMaxDynamicSharedMemorySize, GEMM_SMEM);

    // weight pre-split (independent of activations; launch first)
    split_w<<<(DMODEL*3*DMODEL/4)/256, 256>>>(Wqkv, wqh, wql, DMODEL*3*DMODEL/4);
    split_w<<<(DMODEL*DMODEL/4)/256, 256>>>(Wout, woh, wol, DMODEL*DMODEL/4);
    split_w<<<(DMODEL*DFF/4)/256, 256>>>(W1, w1h, w1l, DMODEL*DFF/4);
    split_w<<<(DFF*DMODEL/4)/256, 256>>>(W2, w2h, w2l, DFF*DMODEL/4);

    // K0: modulation
    ada_kernel<<<MODW / 256, 256>>>(c, ada_W, ada_b, mod_p);

    // K1: LN1 + modulate -> xn split planes
    ln_mod_kernel<<<TOKENS, 256>>>(x, norm1_w, mod_p, 0, 1024, xnh, xnl);

    // K2: QKV GEMM (8192 x 3072 x 1024) -> fp32 qkv
    mma_gemm<0><<<dim3(3 * DMODEL / 128, TOKENS / 128), 256, GEMM_SMEM>>>(
        xnh, xnl, wqh, wql, qkv_p, nullptr, nullptr,
        TOKENS, 3 * DMODEL, DMODEL, nullptr, nullptr, nullptr, 0);

    // K3: RMSNorm + RoPE on q,k
    rope_kernel<<<TOKENS * NHEAD * 2 / 8, 256>>>(qkv_p, cosb, sinb, q_norm_w, k_norm_w);

    // K4: attention -> attn split planes
    int smem = (3 * 64 * 65 + 64 * 64 + 3 * 64) * sizeof(float);  // 67072 B
    cudaFuncSetAttribute(flash_attn, cudaFuncAttributeMaxDynamicSharedMemorySize, smem);
    flash_attn<<<dim3(BATCH * NHEAD, SEQ / 64), 256, smem>>>(qkv_p, ath, atl);

    // K5: Wout GEMM + gated residual (g_msa @2048) -> out fp32
    mma_gemm<2><<<dim3(DMODEL / 128, TOKENS / 128), 256, GEMM_SMEM>>>(
        ath, atl, woh, wol, out, nullptr, nullptr,
        TOKENS, DMODEL, DMODEL, nullptr, x, mod_p, 2048);

    // K6: LN2 + modulate -> xn split planes
    ln_mod_kernel<<<TOKENS, 256>>>(out, norm2_w, mod_p, 3072, 4096, xnh, xnl);

    // K7: MLP up GEMM + bias + gelu -> h split planes
    mma_gemm<1><<<dim3(DFF / 128, TOKENS / 128), 256, GEMM_SMEM>>>(
        xnh, xnl, w1h, w1l, nullptr, hh, hl,
        TOKENS, DFF, DMODEL, b1, nullptr, nullptr, 0);

    // K8: MLP down GEMM + bias + gated residual (g_mlp @5120), in-place on out
    mma_gemm<3><<<dim3(DMODEL / 128, TOKENS / 128), 256, GEMM_SMEM>>>(
        hh, hl, w2h, w2l, out, nullptr, nullptr,
        TOKENS, DMODEL, DFF, b2, out, mod_p, 5120);
}

// round 14
// speedup vs baseline: 2.8259x; 1.6984x over previous
#include <cuda_runtime.h>
#include <cuda_bf16.h>
#include <math.h>
#include <stdint.h>

// Problem constants
#define BATCH 4
#define SEQ   2048
#define DMODEL 1024
#define NHEAD 16
#define HDIM  64
#define DFF   4096
#define TOKENS (BATCH*SEQ)       // 8192
#define MODW  6144               // 6*D

// ---------------- scratch (device globals; no allocations allowed) ----------
__device__ float g_mod[BATCH * MODW];
__device__ float g_qkv[(size_t)TOKENS * 3 * DMODEL];
__device__ __nv_bfloat16 g_xn_hi[(size_t)TOKENS * DMODEL];
__device__ __nv_bfloat16 g_xn_lo[(size_t)TOKENS * DMODEL];
__device__ __nv_bfloat16 g_attn_hi[(size_t)TOKENS * DMODEL];
__device__ __nv_bfloat16 g_attn_lo[(size_t)TOKENS * DMODEL];
__device__ __nv_bfloat16 g_h_hi[(size_t)TOKENS * DFF];
__device__ __nv_bfloat16 g_h_lo[(size_t)TOKENS * DFF];
__device__ __nv_bfloat16 g_wqkv_hi[(size_t)DMODEL * 3 * DMODEL];
__device__ __nv_bfloat16 g_wqkv_lo[(size_t)DMODEL * 3 * DMODEL];
__device__ __nv_bfloat16 g_wout_hi[(size_t)DMODEL * DMODEL];
__device__ __nv_bfloat16 g_wout_lo[(size_t)DMODEL * DMODEL];
__device__ __nv_bfloat16 g_w1_hi[(size_t)DMODEL * DFF];
__device__ __nv_bfloat16 g_w1_lo[(size_t)DMODEL * DFF];
__device__ __nv_bfloat16 g_w2_hi[(size_t)DFF * DMODEL];
__device__ __nv_bfloat16 g_w2_lo[(size_t)DFF * DMODEL];
// attention operand planes, layout [B][H][S][HD]
__device__ __nv_bfloat16 g_q_hi[(size_t)TOKENS * DMODEL];
__device__ __nv_bfloat16 g_q_lo[(size_t)TOKENS * DMODEL];
__device__ __nv_bfloat16 g_k_hi[(size_t)TOKENS * DMODEL];
__device__ __nv_bfloat16 g_k_lo[(size_t)TOKENS * DMODEL];
__device__ __nv_bfloat16 g_v_hi[(size_t)TOKENS * DMODEL];
__device__ __nv_bfloat16 g_v_lo[(size_t)TOKENS * DMODEL];

// ---------------- generic helpers -------------------------------------------
__device__ __forceinline__ float warpSum(float v) {
    v += __shfl_xor_sync(0xffffffffu, v, 16);
    v += __shfl_xor_sync(0xffffffffu, v, 8);
    v += __shfl_xor_sync(0xffffffffu, v, 4);
    v += __shfl_xor_sync(0xffffffffu, v, 2);
    v += __shfl_xor_sync(0xffffffffu, v, 1);
    return v;
}

__device__ __forceinline__ float gelu_tanh(float x) {
    float x3 = x * x * x;
    return 0.5f * x * (1.0f + tanhf(0.7978845608028654f * (x + 0.044715f * x3)));
}

__device__ __forceinline__ uint32_t smem_u32(const void* p) {
    uint32_t a;
    asm("{ .reg .u64 t; cvta.to.shared.u64 t, %1; cvt.u32.u64 %0, t; }" : "=r"(a) : "l"(p));
    return a;
}

// fp32 -> (hi, lo) bf16 pair, packed two-at-a-time into b32 (a in low half)
__device__ __forceinline__ uint32_t split_pack(float a, float b, uint32_t& lo) {
    __nv_bfloat16 ha = __float2bfloat16(a), hb = __float2bfloat16(b);
    float ra = a - __bfloat162float(ha);
    float rb = b - __bfloat162float(hb);
    __nv_bfloat16 la = __float2bfloat16(ra), lb = __float2bfloat16(rb);
    lo = (uint32_t)__bfloat16_as_ushort(la) | ((uint32_t)__bfloat16_as_ushort(lb) << 16);
    return (uint32_t)__bfloat16_as_ushort(ha) | ((uint32_t)__bfloat16_as_ushort(hb) << 16);
}

__device__ __forceinline__ void split_store1(__nv_bfloat16* hi, __nv_bfloat16* lo,
                                             size_t idx, float v) {
    __nv_bfloat16 h = __float2bfloat16(v);
    hi[idx] = h;
    lo[idx] = __float2bfloat16(v - __bfloat162float(h));
}

__device__ __forceinline__ void split_store2(__nv_bfloat16* hi, __nv_bfloat16* lo,
                                             size_t idx, float a, float b) {
    __nv_bfloat16 ha = __float2bfloat16(a), hb = __float2bfloat16(b);
    __nv_bfloat162 hv; hv.x = ha; hv.y = hb;
    *(__nv_bfloat162*)&hi[idx] = hv;
    __nv_bfloat162 lv;
    lv.x = __float2bfloat16(a - __bfloat162float(ha));
    lv.y = __float2bfloat16(b - __bfloat162float(hb));
    *(__nv_bfloat162*)&lo[idx] = lv;
}

// ---------------- warp-level MMA primitives (sm_80+, no 'a' features) --------
__device__ __forceinline__ void ldsm4(uint32_t* r, uint32_t a) {
    asm volatile("ldmatrix.sync.aligned.m8n8.x4.shared.b16 {%0,%1,%2,%3}, [%4];"
        : "=r"(r[0]), "=r"(r[1]), "=r"(r[2]), "=r"(r[3]) : "r"(a));
}
__device__ __forceinline__ void ldsm4t(uint32_t* r, uint32_t a) {
    asm volatile("ldmatrix.sync.aligned.m8n8.x4.trans.shared.b16 {%0,%1,%2,%3}, [%4];"
        : "=r"(r[0]), "=r"(r[1]), "=r"(r[2]), "=r"(r[3]) : "r"(a));
}
__device__ __forceinline__ void mma16816(float* c, const uint32_t* a, const uint32_t* b) {
    asm volatile(
        "mma.sync.aligned.m16n8k16.row.col.f32.bf16.bf16.f32 "
        "{%0,%1,%2,%3}, {%4,%5,%6,%7}, {%8,%9}, {%0,%1,%2,%3};"
        : "+f"(c[0]), "+f"(c[1]), "+f"(c[2]), "+f"(c[3])
        : "r"(a[0]), "r"(a[1]), "r"(a[2]), "r"(a[3]), "r"(b[0]), "r"(b[1]));
}

__device__ __forceinline__ void cpa16(uint32_t s, const void* g) {
    asm volatile("cp.async.cg.shared.global [%0], [%1], 16;" :: "r"(s), "l"(g));
}
#define CP_COMMIT() asm volatile("cp.async.commit_group;" ::: "memory")
#define CP_WAIT1()  asm volatile("cp.async.wait_group 1;" ::: "memory")
#define CP_WAIT0()  asm volatile("cp.async.wait_group 0;" ::: "memory")

// ---------------- K-1: weight pre-split (fp32 -> bf16 hi/lo planes) ----------
__global__ void split_w(const float* __restrict__ W,
                        __nv_bfloat16* __restrict__ hi,
                        __nv_bfloat16* __restrict__ lo, int n4) {
    int i = blockIdx.x * 256 + threadIdx.x;
    if (i >= n4) return;
    float4 v = ((const float4*)W)[i];
    uint32_t l0, l1;
    uint32_t h0 = split_pack(v.x, v.y, l0);
    uint32_t h1 = split_pack(v.z, v.w, l1);
    ((uint2*)hi)[i] = make_uint2(h0, h1);
    ((uint2*)lo)[i] = make_uint2(l0, l1);
}

// ---------------- K0: adaLN modulation ---------------------------------------
__global__ void ada_kernel(const float* __restrict__ c,
                           const float* __restrict__ W,
                           const float* __restrict__ bias,
                           float* __restrict__ mod) {
    __shared__ float cs[BATCH * 1024];
    int tid = threadIdx.x;
    for (int i = tid; i < BATCH * 1024; i += 256) cs[i] = c[i];
    __syncthreads();
    int n = blockIdx.x * 256 + tid;
    float a0 = 0.f, a1 = 0.f, a2 = 0.f, a3 = 0.f;
    #pragma unroll 4
    for (int k = 0; k < 1024; k++) {
        float w = W[(size_t)k * MODW + n];
        a0 += cs[k] * w;
        a1 += cs[1024 + k] * w;
        a2 += cs[2048 + k] * w;
        a3 += cs[3072 + k] * w;
    }
    float bb = bias[n];
    mod[n] = a0 + bb;
    mod[MODW + n] = a1 + bb;
    mod[2 * MODW + n] = a2 + bb;
    mod[3 * MODW + n] = a3 + bb;
}

// ---------------- K1: LayerNorm + modulate -> split bf16 planes --------------
__global__ void ln_mod_kernel(const float* __restrict__ x,
                              const float* __restrict__ w,
                              const float* __restrict__ mod,
                              int shOff, int scOff,
                              __nv_bfloat16* __restrict__ ohi,
                              __nv_bfloat16* __restrict__ olo) {
    int token = blockIdx.x;
    int b = token >> 11;
    int tid = threadIdx.x;
    const float* xr = x + (size_t)token * DMODEL;
    float v[4];
    float lsum = 0.f, lsq = 0.f;
    #pragma unroll
    for (int i = 0; i < 4; i++) {
        v[i] = xr[i * 256 + tid];
        lsum += v[i];
        lsq  += v[i] * v[i];
    }
    __shared__ float s1[8], s2[8];
    float ws = warpSum(lsum), wq = warpSum(lsq);
    int warp = tid >> 5, lane = tid & 31;
    if (lane == 0) { s1[warp] = ws; s2[warp] = wq; }
    __syncthreads();
    __shared__ float s_mu, s_rstd;
    if (tid == 0) {
        float ts = 0.f, tq = 0.f;
        #pragma unroll
        for (int i = 0; i < 8; i++) { ts += s1[i]; tq += s2[i]; }
        float mu = ts * (1.0f / DMODEL);
        float var = tq * (1.0f / DMODEL) - mu * mu;
        s_mu = mu;
        s_rstd = rsqrtf(var + 1e-5f);
    }
    __syncthreads();
    float mu = s_mu, rstd = s_rstd;
    const float* mrow = mod + (size_t)b * MODW;
    size_t rowoff = (size_t)token * DMODEL;
    #pragma unroll
    for (int i = 0; i < 4; i++) {
        int d = i * 256 + tid;
        float xn = (v[i] - mu) * rstd * w[d];
        float val = xn * (1.f + mrow[scOff + d]) + mrow[shOff + d];
        split_store1(ohi, olo, rowoff + d, val);
    }
}

// ---------------- K2: split-bf16 HMMA GEMM, cp.async double-buffered ---------
#define AST    80
#define BSTB   272
#define A_LO_OFF 10240
#define B_HI_OFF 20480
#define STAGE  37888
#define GEMM_SMEM (2 * STAGE)   // 75776

template <int EPI>
__device__ __forceinline__ float epi_apply(float v, int m, int n, int N,
        const float* __restrict__ bias, const float* __restrict__ resid,
        const float* __restrict__ mod, int modOff) {
    if (EPI == 2) v = resid[(size_t)m * N + n]
                    + mod[(size_t)(m >> 11) * MODW + modOff + n] * v;
    if (EPI == 3) v = resid[(size_t)m * N + n]
                    + mod[(size_t)(m >> 11) * MODW + modOff + n] * (v + bias[n]);
    return v;
}

// EPI 0: C(fp32) = A@B
// EPI 1: Chi/Clo(bf16 split) = gelu(A@B + bias)
// EPI 2: C = resid + mod[b, modOff+n] * (A@B)              (N == 1024)
// EPI 3: C = resid + mod[b, modOff+n] * (A@B + bias)       (N == 1024)
template <int EPI>
__global__ void __launch_bounds__(256, 2)
mma_gemm(const __nv_bfloat16* __restrict__ Ahg, const __nv_bfloat16* __restrict__ Alg,
         const __nv_bfloat16* __restrict__ Bhg, const __nv_bfloat16* __restrict__ Blg,
         float* __restrict__ C,
         __nv_bfloat16* __restrict__ Chi, __nv_bfloat16* __restrict__ Clo,
         int M, int N, int K,
         const float* __restrict__ bias,
         const float* __restrict__ resid,
         const float* __restrict__ mod, int modOff) {
    extern __shared__ char smem[];
    uint32_t sb = smem_u32(smem);
    int tid = threadIdx.x, lane = tid & 31, wid = tid >> 5;
    int wm = wid >> 1, wn = wid & 1;
    int m0 = blockIdx.y * 128, n0 = blockIdx.x * 128;

    float acc[2][8][4];
    #pragma unroll
    for (int i = 0; i < 2; i++)
        #pragma unroll
        for (int j = 0; j < 8; j++)
            #pragma unroll
            for (int k = 0; k < 4; k++) acc[i][j][k] = 0.f;

    int s0 = tid * 2;
    int arow0 = s0 >> 2,  aoff0 = s0 & 3;
    int arow1 = (s0+1) >> 2, aoff1 = (s0+1) & 3;
    int brow0 = s0 >> 4,  boff0 = s0 & 15;
    int brow1 = (s0+1) >> 4, boff1 = (s0+1) & 15;

    uint32_t aBase = sb + (uint32_t)(wm * 32 + (lane & 15)) * AST + (uint32_t)((lane >> 4) * 8) * 2;
    int bg = lane >> 3;
    uint32_t bBase = sb + B_HI_OFF
                   + (uint32_t)((bg & 1) * 8 + (lane & 7)) * BSTB
                   + (uint32_t)(wn * 64 + ((bg >> 1) & 1) * 8) * 2;

    const int nc = K >> 5;

    auto load_stage = [&](int c, int st) {
        int k0 = c << 5;
        uint32_t sA = sb + st * STAGE;
        uint32_t sB = sA + B_HI_OFF;
        const __nv_bfloat16* g;
        uint32_t d;
        g = Ahg + (size_t)(m0 + arow0) * K + k0 + aoff0 * 8;
        d = sA + arow0 * AST + aoff0 * 16;
        cpa16(d, g);
        g = Alg + (size_t)(m0 + arow0) * K + k0 + aoff0 * 8;
        cpa16(d + A_LO_OFF, g);
        g = Ahg + (size_t)(m0 + arow1) * K + k0 + aoff1 * 8;
        d = sA + arow1 * AST + aoff1 * 16;
        cpa16(d, g);
        g = Alg + (size_t)(m0 + arow1) * K + k0 + aoff1 * 8;
        cpa16(d + A_LO_OFF, g);
        g = Bhg + (size_t)(k0 + brow0) * N + n0 + boff0 * 8;
        d = sB + brow0 * BSTB + boff0 * 16;
        cpa16(d, g);
        g = Blg + (size_t)(k0 + brow0) * N + n0 + boff0 * 8;
        cpa16(d + 8704, g);
        g = Bhg + (size_t)(k0 + brow1) * N + n0 + boff1 * 8;
        d = sB + brow1 * BSTB + boff1 * 16;
        cpa16(d, g);
        g = Blg + (size_t)(k0 + brow1) * N + n0 + boff1 * 8;
        cpa16(d + 8704, g);
    };

    load_stage(0, 0);
    CP_COMMIT();

    for (int c = 0; c < nc; c++) {
        if (c + 1 < nc) {
            load_stage(c + 1, (c + 1) & 1);
            CP_COMMIT();
            CP_WAIT1();
        } else {
            CP_WAIT0();
        }
        __syncthreads();

        uint32_t stOff = (uint32_t)(c & 1) * STAGE;
        #pragma unroll
        for (int ks = 0; ks < 2; ks++) {
            uint32_t ah[2][4], al[2][4];
            #pragma unroll
            for (int mt = 0; mt < 2; mt++) {
                ldsm4(ah[mt], aBase + stOff + mt * 16 * AST + ks * 32);
                ldsm4(al[mt], aBase + stOff + A_LO_OFF + mt * 16 * AST + ks * 32);
            }
            #pragma unroll
            for (int q = 0; q < 4; q++) {
                uint32_t bh[4], bl[4];
                ldsm4t(bh, bBase + stOff + q * 32 + ks * 16 * BSTB);
                ldsm4t(bl, bBase + stOff + 8704 + q * 32 + ks * 16 * BSTB);
                #pragma unroll
                for (int mt = 0; mt < 2; mt++) {
                    mma16816(acc[mt][2 * q],     ah[mt], bh);
                    mma16816(acc[mt][2 * q],     ah[mt], bl);
                    mma16816(acc[mt][2 * q],     al[mt], bh);
                    mma16816(acc[mt][2 * q + 1], ah[mt], bh + 2);
                    mma16816(acc[mt][2 * q + 1], ah[mt], bl + 2);
                    mma16816(acc[mt][2 * q + 1], al[mt], bh + 2);
                }
            }
        }
        __syncthreads();
    }

    int r0 = lane >> 2, cp2 = (lane & 3) * 2;
    #pragma unroll
    for (int mt = 0; mt < 2; mt++) {
        #pragma unroll
        for (int nt = 0; nt < 8; nt++) {
            int m = m0 + wm * 32 + mt * 16 + r0;
            int n = n0 + wn * 64 + nt * 8 + cp2;
            float* cacc = acc[mt][nt];
            if (EPI == 1) {
                float v00 = gelu_tanh(cacc[0] + bias[n]);
                float v01 = gelu_tanh(cacc[1] + bias[n + 1]);
                float v10 = gelu_tanh(cacc[2] + bias[n]);
                float v11 = gelu_tanh(cacc[3] + bias[n + 1]);
                split_store2(Chi, Clo, (size_t)m * N + n, v00, v01);
                split_store2(Chi, Clo, (size_t)(m + 8) * N + n, v10, v11);
            } else {
                float2 o0, o1;
                o0.x = epi_apply<EPI>(cacc[0], m, n,     N, bias, resid, mod, modOff);
                o0.y = epi_apply<EPI>(cacc[1], m, n + 1, N, bias, resid, mod, modOff);
                o1.x = epi_apply<EPI>(cacc[2], m + 8, n,     N, bias, resid, mod, modOff);
                o1.y = epi_apply<EPI>(cacc[3], m + 8, n + 1, N, bias, resid, mod, modOff);
                *(float2*)&C[(size_t)m * N + n] = o0;
                *(float2*)&C[(size_t)(m + 8) * N + n] = o1;
            }
        }
    }
}

// ---------------- K3: RMSNorm + RoPE -> split planes [B][H][S][HD] -----------
// one warp per (token, head, {q|k|v}); q pre-scaled by 0.125*log2(e)
__global__ void rope_split_kernel(const float* __restrict__ qkv,
                                  const float* __restrict__ cosb,
                                  const float* __restrict__ sinb,
                                  const float* __restrict__ qw,
                                  const float* __restrict__ kw,
                                  __nv_bfloat16* __restrict__ qh, __nv_bfloat16* __restrict__ ql,
                                  __nv_bfloat16* __restrict__ kh, __nv_bfloat16* __restrict__ kl,
                                  __nv_bfloat16* __restrict__ vh, __nv_bfloat16* __restrict__ vl) {
    int gwid = blockIdx.x * 8 + (threadIdx.x >> 5);
    int lane = threadIdx.x & 31;
    int bs = gwid / 48;
    int rem = gwid - bs * 48;
    int h = rem / 3;
    int t = rem - h * 3;
    int s = bs & (SEQ - 1);
    int b = bs >> 11;
    const float* src = qkv + (size_t)bs * 3072 + t * 1024 + h * 64;
    size_t doff = (((size_t)(b * NHEAD + h)) * SEQ + s) * HDIM;
    if (t == 2) {
        float a = src[lane * 2], b2 = src[lane * 2 + 1];
        split_store2(vh, vl, doff + lane * 2, a, b2);
        return;
    }
    const float* w = (t == 0) ? qw : kw;
    float x0 = src[lane];
    float x1 = src[lane + 32];
    float ss = warpSum(x0 * x0 + x1 * x1);
    float rinv = rsqrtf(ss * (1.0f / HDIM) + 1e-6f);
    float n0 = x0 * rinv * w[lane];
    float n1 = x1 * rinv * w[lane + 32];
    const float* cr = cosb + (size_t)s * HDIM;
    const float* sr = sinb + (size_t)s * HDIM;
    float c0 = cr[lane], c1 = cr[lane + 32];
    float s0 = sr[lane], s1 = sr[lane + 32];
    float r0 = n0 * c0 - n1 * s0;
    float r1 = n1 * c1 + n0 * s1;
    if (t == 0) {
        const float SC = 0.125f * 1.4426950408889634f;
        r0 *= SC; r1 *= SC;
        split_store1(qh, ql, doff + lane, r0);
        split_store1(qh, ql, doff + lane + 32, r1);
    } else {
        split_store1(kh, kl, doff + lane, r0);
        split_store1(kh, kl, doff + lane + 32, r1);
    }
}

// ---------------- K4: HMMA flash attention -----------------------------------
// 128 queries/CTA, 8 warps x 16 rows. K/V tiles: 64 keys, double buffered.
// smem stage (per stage 36864B): K_hi@0, K_lo@9216, V_hi@18432, V_lo@27648
// rows padded to 144 B (72 halves). Q staged once in stage0 then held in regs.
#define FST   144
#define FSTAGE 36864
#define FLASH_SMEM (2 * FSTAGE)   // 73728

__global__ void __launch_bounds__(256, 2)
flash_mma(const __nv_bfloat16* __restrict__ qh, const __nv_bfloat16* __restrict__ ql,
          const __nv_bfloat16* __restrict__ kh, const __nv_bfloat16* __restrict__ kl,
          const __nv_bfloat16* __restrict__ vh, const __nv_bfloat16* __restrict__ vl,
          __nv_bfloat16* __restrict__ ohi, __nv_bfloat16* __restrict__ olo) {
    extern __shared__ char smem[];
    uint32_t sb = smem_u32(smem);
    int tid = threadIdx.x, lane = tid & 31, wid = tid >> 5;
    int bhid = blockIdx.x;               // b*16 + h
    int h = bhid & 15, b = bhid >> 4;
    int q0 = blockIdx.y * 128;
    size_t hoff = (size_t)bhid * SEQ * HDIM;

    // ---- Q -> smem (stage0 region) -> registers ----
    #pragma unroll
    for (int i = 0; i < 4; i++) {
        int c = tid + i * 256;            // 1024 chunks per plane
        int row = c >> 3, col = c & 7;
        cpa16(sb + row * FST + col * 16, qh + hoff + (size_t)(q0 + row) * HDIM + col * 8);
        cpa16(sb + 18432 + row * FST + col * 16, ql + hoff + (size_t)(q0 + row) * HDIM + col * 8);
    }
    CP_COMMIT(); CP_WAIT0();
    __syncthreads();
    uint32_t qfh[4][4], qfl[4][4];
    {
        uint32_t aB = sb + (uint32_t)(wid * 16 + (lane & 15)) * FST + (uint32_t)((lane >> 4) * 16);
        #pragma unroll
        for (int kt = 0; kt < 4; kt++) {
            ldsm4(qfh[kt], aB + kt * 32);
            ldsm4(qfl[kt], aB + 18432 + kt * 32);
        }
    }
    __syncthreads();

    float o[8][4];
    #pragma unroll
    for (int i = 0; i < 8; i++)
        #pragma unroll
        for (int j = 0; j < 4; j++) o[i][j] = 0.f;
    float m0 = -1e30f, m1 = -1e30f, l0 = 0.f, l1 = 0.f;

    // ldmatrix lane bases (within a stage)
    uint32_t kB = (uint32_t)((lane & 7) + ((lane >> 4) << 3)) * FST + (uint32_t)(((lane >> 3) & 1) << 4);
    int bg = lane >> 3;
    uint32_t vB = (uint32_t)((bg & 1) * 8 + (lane & 7)) * FST + (uint32_t)(((bg >> 1)) << 4);

    // K/V stage loader: 512 chunks per plane / 256 thr = 2 each
    auto load_kv = [&](int t, int st) {
        int k0 = t * 64;
        uint32_t sbase = sb + st * FSTAGE;
        #pragma unroll
        for (int i = 0; i < 2; i++) {
            int c = tid + i * 256;
            int row = c >> 3, col = c & 7;
            size_t goff = hoff + (size_t)(k0 + row) * HDIM + col * 8;
            uint32_t d = sbase + row * FST + col * 16;
            cpa16(d, kh + goff);
            cpa16(d + 9216, kl + goff);
            cpa16(d + 18432, vh + goff);
            cpa16(d + 27648, vl + goff);
        }
    };

    load_kv(0, 0);
    CP_COMMIT();

    const int NT = SEQ / 64;
    for (int t = 0; t < NT; t++) {
        if (t + 1 < NT) {
            load_kv(t + 1, (t + 1) & 1);
            CP_COMMIT();
            CP_WAIT1();
        } else {
            CP_WAIT0();
        }
        __syncthreads();
        uint32_t stB = sb + (uint32_t)(t & 1) * FSTAGE;

        // ---- S = Q K^T (split, 3 passes) ----
        float s[8][4];
        #pragma unroll
        for (int i = 0; i < 8; i++)
            #pragma unroll
            for (int j = 0; j < 4; j++) s[i][j] = 0.f;
        #pragma unroll
        for (int kt = 0; kt < 4; kt++) {
            #pragma unroll
            for (int kg = 0; kg < 4; kg++) {
                uint32_t fh[4], fl[4];
                uint32_t addr = stB + kB + kg * (16 * FST) + kt * 32;
                ldsm4(fh, addr);
                ldsm4(fl, addr + 9216);
                mma16816(s[kg * 2],     qfh[kt], fh);
                mma16816(s[kg * 2],     qfh[kt], fl);
                mma16816(s[kg * 2],     qfl[kt], fh);
                mma16816(s[kg * 2 + 1], qfh[kt], fh + 2);
                mma16816(s[kg * 2 + 1], qfh[kt], fl + 2);
                mma16816(s[kg * 2 + 1], qfl[kt], fh + 2);
            }
        }

        // ---- online softmax (base-2; scale folded into Q) ----
        float tm0 = -1e30f, tm1 = -1e30f;
        #pragma unroll
        for (int i = 0; i < 8; i++) {
            tm0 = fmaxf(tm0, fmaxf(s[i][0], s[i][1]));
            tm1 = fmaxf(tm1, fmaxf(s[i][2], s[i][3]));
        }
        tm0 = fmaxf(tm0, __shfl_xor_sync(0xffffffffu, tm0, 1));
        tm0 = fmaxf(tm0, __shfl_xor_sync(0xffffffffu, tm0, 2));
        tm1 = fmaxf(tm1, __shfl_xor_sync(0xffffffffu, tm1, 1));
        tm1 = fmaxf(tm1, __shfl_xor_sync(0xffffffffu, tm1, 2));
        float mn0 = fmaxf(m0, tm0), mn1 = fmaxf(m1, tm1);
        float al0 = exp2f(m0 - mn0), al1 = exp2f(m1 - mn1);
        float ts0 = 0.f, ts1 = 0.f;
        #pragma unroll
        for (int i = 0; i < 8; i++) {
            s[i][0] = exp2f(s[i][0] - mn0);
            s[i][1] = exp2f(s[i][1] - mn0);
            s[i][2] = exp2f(s[i][2] - mn1);
            s[i][3] = exp2f(s[i][3] - mn1);
            ts0 += s[i][0] + s[i][1];
            ts1 += s[i][2] + s[i][3];
        }
        ts0 += __shfl_xor_sync(0xffffffffu, ts0, 1);
        ts0 += __shfl_xor_sync(0xffffffffu, ts0, 2);
        ts1 += __shfl_xor_sync(0xffffffffu, ts1, 1);
        ts1 += __shfl_xor_sync(0xffffffffu, ts1, 2);
        l0 = l0 * al0 + ts0;
        l1 = l1 * al1 + ts1;
        m0 = mn0; m1 = mn1;
        #pragma unroll
        for (int i = 0; i < 8; i++) {
            o[i][0] *= al0; o[i][1] *= al0;
            o[i][2] *= al1; o[i][3] *= al1;
        }

        // ---- O += P V (split P in-register, split V, 3 passes) ----
        #pragma unroll
        for (int kt2 = 0; kt2 < 4; kt2++) {
            uint32_t ph[4], pl[4];
            ph[0] = split_pack(s[kt2 * 2][0],     s[kt2 * 2][1],     pl[0]);
            ph[1] = split_pack(s[kt2 * 2][2],     s[kt2 * 2][3],     pl[1]);
            ph[2] = split_pack(s[kt2 * 2 + 1][0], s[kt2 * 2 + 1][1], pl[2]);
            ph[3] = split_pack(s[kt2 * 2 + 1][2], s[kt2 * 2 + 1][3], pl[3]);
            #pragma unroll
            for (int nq = 0; nq < 4; nq++) {
                uint32_t wh[4], wl[4];
                uint32_t addr = stB + 18432 + vB + kt2 * (16 * FST) + nq * 32;
                ldsm4t(wh, addr);
                ldsm4t(wl, addr + 9216);
                mma16816(o[nq * 2],     ph, wh);
                mma16816(o[nq * 2],     pl, wh);
                mma16816(o[nq * 2],     ph, wl);
                mma16816(o[nq * 2 + 1], ph, wh + 2);
                mma16816(o[nq * 2 + 1], pl, wh + 2);
                mma16816(o[nq * 2 + 1], ph, wl + 2);
            }
        }
        __syncthreads();
    }

    // ---- normalize + split store to attn planes [token][D] ----
    float inv0 = 1.f / l0, inv1 = 1.f / l1;
    int r0 = lane >> 2, cp2 = (lane & 3) * 2;
    int row0 = q0 + wid * 16 + r0;
    size_t t0 = (size_t)(b * SEQ + row0) * DMODEL + h * HDIM;
    size_t t1 = t0 + 8 * DMODEL;
    #pragma unroll
    for (int nt = 0; nt < 8; nt++) {
        split_store2(ohi, olo, t0 + nt * 8 + cp2, o[nt][0] * inv0, o[nt][1] * inv0);
        split_store2(ohi, olo, t1 + nt * 8 + cp2, o[nt][2] * inv1, o[nt][3] * inv1);
    }
}

// ---------------- launcher ---------------------------------------------------
extern "C" void kernel_launch(void* const* d_in, const int* in_sizes, int n_in,
                              void* d_out, int out_size) {
    const float* x       = (const float*)d_in[0];
    const float* cosb    = (const float*)d_in[1];
    const float* sinb    = (const float*)d_in[2];
    const float* c       = (const float*)d_in[3];
    const float* norm1_w = (const float*)d_in[4];
    const float* Wqkv    = (const float*)d_in[5];
    const float* Wout    = (const float*)d_in[6];
    const float* q_norm_w= (const float*)d_in[7];
    const float* k_norm_w= (const float*)d_in[8];
    const float* norm2_w = (const float*)d_in[9];
    const float* W1      = (const float*)d_in[10];
    const float* b1      = (const float*)d_in[11];
    const float* W2      = (const float*)d_in[12];
    const float* b2      = (const float*)d_in[13];
    const float* ada_W   = (const float*)d_in[14];
    const float* ada_b   = (const float*)d_in[15];
    float* out = (float*)d_out;

    float *mod_p, *qkv_p;
    __nv_bfloat16 *xnh, *xnl, *ath, *atl, *hh, *hl;
    __nv_bfloat16 *wqh, *wql, *woh, *wol, *w1h, *w1l, *w2h, *w2l;
    __nv_bfloat16 *qph, *qpl, *kph, *kpl, *vph, *vpl;
    cudaGetSymbolAddress((void**)&mod_p, g_mod);
    cudaGetSymbolAddress((void**)&qkv_p, g_qkv);
    cudaGetSymbolAddress((void**)&xnh, g_xn_hi);
    cudaGetSymbolAddress((void**)&xnl, g_xn_lo);
    cudaGetSymbolAddress((void**)&ath, g_attn_hi);
    cudaGetSymbolAddress((void**)&atl, g_attn_lo);
    cudaGetSymbolAddress((void**)&hh, g_h_hi);
    cudaGetSymbolAddress((void**)&hl, g_h_lo);
    cudaGetSymbolAddress((void**)&wqh, g_wqkv_hi);
    cudaGetSymbolAddress((void**)&wql, g_wqkv_lo);
    cudaGetSymbolAddress((void**)&woh, g_wout_hi);
    cudaGetSymbolAddress((void**)&wol, g_wout_lo);
    cudaGetSymbolAddress((void**)&w1h, g_w1_hi);
    cudaGetSymbolAddress((void**)&w1l, g_w1_lo);
    cudaGetSymbolAddress((void**)&w2h, g_w2_hi);
    cudaGetSymbolAddress((void**)&w2l, g_w2_lo);
    cudaGetSymbolAddress((void**)&qph, g_q_hi);
    cudaGetSymbolAddress((void**)&qpl, g_q_lo);
    cudaGetSymbolAddress((void**)&kph, g_k_hi);
    cudaGetSymbolAddress((void**)&kpl, g_k_lo);
    cudaGetSymbolAddress((void**)&vph, g_v_hi);
    cudaGetSymbolAddress((void**)&vpl, g_v_lo);

    cudaFuncSetAttribute(mma_gemm<0>, cudaFuncAttributeMaxDynamicSharedMemorySize, GEMM_SMEM);
    cudaFuncSetAttribute(mma_gemm<1>, cudaFuncAttributeMaxDynamicSharedMemorySize, GEMM_SMEM);
    cudaFuncSetAttribute(mma_gemm<2>, cudaFuncAttributeMaxDynamicSharedMemorySize, GEMM_SMEM);
    cudaFuncSetAttribute(mma_gemm<3>, cudaFuncAttributeMaxDynamicSharedMemorySize, GEMM_SMEM);
    cudaFuncSetAttribute(flash_mma, cudaFuncAttributeMaxDynamicSharedMemorySize, FLASH_SMEM);

    // weight pre-split
    split_w<<<(DMODEL*3*DMODEL/4)/256, 256>>>(Wqkv, wqh, wql, DMODEL*3*DMODEL/4);
    split_w<<<(DMODEL*DMODEL/4)/256, 256>>>(Wout, woh, wol, DMODEL*DMODEL/4);
    split_w<<<(DMODEL*DFF/4)/256, 256>>>(W1, w1h, w1l, DMODEL*DFF/4);
    split_w<<<(DFF*DMODEL/4)/256, 256>>>(W2, w2h, w2l, DFF*DMODEL/4);

    // K0: modulation
    ada_kernel<<<MODW / 256, 256>>>(c, ada_W, ada_b, mod_p);

    // K1: LN1 + modulate -> xn split planes
    ln_mod_kernel<<<TOKENS, 256>>>(x, norm1_w, mod_p, 0, 1024, xnh, xnl);

    // K2: QKV GEMM (8192 x 3072 x 1024) -> fp32 qkv
    mma_gemm<0><<<dim3(3 * DMODEL / 128, TOKENS / 128), 256, GEMM_SMEM>>>(
        xnh, xnl, wqh, wql, qkv_p, nullptr, nullptr,
        TOKENS, 3 * DMODEL, DMODEL, nullptr, nullptr, nullptr, 0);

    // K3: RMSNorm + RoPE + split -> q/k/v planes [B][H][S][HD]
    rope_split_kernel<<<TOKENS * NHEAD * 3 / 8, 256>>>(
        qkv_p, cosb, sinb, q_norm_w, k_norm_w, qph, qpl, kph, kpl, vph, vpl);

    // K4: HMMA flash attention -> attn split planes
    flash_mma<<<dim3(BATCH * NHEAD, SEQ / 128), 256, FLASH_SMEM>>>(
        qph, qpl, kph, kpl, vph, vpl, ath, atl);

    // K5: Wout GEMM + gated residual (g_msa @2048) -> out fp32
    mma_gemm<2><<<dim3(DMODEL / 128, TOKENS / 128), 256, GEMM_SMEM>>>(
        ath, atl, woh, wol, out, nullptr, nullptr,
        TOKENS, DMODEL, DMODEL, nullptr, x, mod_p, 2048);

    // K6: LN2 + modulate -> xn split planes
    ln_mod_kernel<<<TOKENS, 256>>>(out, norm2_w, mod_p, 3072, 4096, xnh, xnl);

    // K7: MLP up GEMM + bias + gelu -> h split planes
    mma_gemm<1><<<dim3(DFF / 128, TOKENS / 128), 256, GEMM_SMEM>>>(
        xnh, xnl, w1h, w1l, nullptr, hh, hl,
        TOKENS, DFF, DMODEL, b1, nullptr, nullptr, 0);

    // K8: MLP down GEMM + bias + gated residual (g_mlp @5120), in-place on out
    mma_gemm<3><<<dim3(DMODEL / 128, TOKENS / 128), 256, GEMM_SMEM>>>(
        hh, hl, w2h, w2l, out, nullptr, nullptr,
        TOKENS, DMODEL, DFF, b2, out, mod_p, 5120);
}